// round 13
// baseline (speedup 1.0000x reference)
#include <cuda_runtime.h>
#include <cuda_bf16.h>
#include <cstdint>
#include <cstddef>

#define BSZ  256
#define TLEN 512
#define DIN  64
#define MTOT (BSZ * TLEN)

typedef __nv_bfloat16 bf16;

// ---------------------------------------------------------------------------
// Device-global scratch
// ---------------------------------------------------------------------------
__device__ float g_xW[MTOT * 1024];            // xW0 = x@W0 + b0, packed cols
__device__ bf16  g_Ahi[MTOT * 64];             // x split (layer-0 GEMM A)
__device__ bf16  g_Alo[MTOT * 64];
__device__ bf16  g_Wthi[458752];               // W^T packed (3 layers), hi
__device__ bf16  g_Wtlo[458752];
__device__ bf16  g_Uthi[589824];               // U^T packed (3 layers)
__device__ bf16  g_Utlo[589824];
__device__ float g_bias[1024];                 // packed b0 (for xW GEMM)
__device__ float g_biasP[1536];                // packed b1 [0:1024), b2 [1024:1536)
__device__ bf16  g_H0hi[MTOT * 256];           // h sequences (bf16 split)
__device__ bf16  g_H0lo[MTOT * 256];
__device__ bf16  g_H1hi[MTOT * 256];
__device__ bf16  g_H1lo[MTOT * 256];
__device__ bf16  g_H2hi[MTOT * 128];
__device__ bf16  g_H2lo[MTOT * 128];
__device__ unsigned int g_prog[8];             // [0..3]=L0 bb, [4..7]=L1 bb
__device__ unsigned int g_bcnt[12 * 32];       // 12 group-barrier slots, padded
__device__ unsigned int g_bgen[12 * 32];

#define WOFF0 0
#define WOFF1 (1024 * 64)
#define WOFF2 (1024 * 64 + 1024 * 256)
#define UOFF0 0
#define UOFF1 (1024 * 256)
#define UOFF2 (2 * 1024 * 256)

// ---------------------------------------------------------------------------
// sm_100-safe helpers (ldmatrix + mma.sync; no tcgen05)
// ---------------------------------------------------------------------------
__device__ __forceinline__ uint32_t smem_u32(const void* p) {
    uint32_t a;
    asm("{ .reg .u64 t; cvta.to.shared.u64 t, %1; cvt.u32.u64 %0, t; }"
        : "=r"(a) : "l"(p));
    return a;
}
__device__ __forceinline__ void ldsm_x4(uint32_t* r, uint32_t addr) {
    asm volatile("ldmatrix.sync.aligned.m8n8.x4.shared.b16 {%0,%1,%2,%3}, [%4];"
                 : "=r"(r[0]), "=r"(r[1]), "=r"(r[2]), "=r"(r[3]) : "r"(addr));
}
__device__ __forceinline__ void ldsm_x2(uint32_t* r, uint32_t addr) {
    asm volatile("ldmatrix.sync.aligned.m8n8.x2.shared.b16 {%0,%1}, [%2];"
                 : "=r"(r[0]), "=r"(r[1]) : "r"(addr));
}
__device__ __forceinline__ void mma_16816(float* d, const uint32_t* a, const uint32_t* b) {
    asm volatile(
        "mma.sync.aligned.m16n8k16.row.col.f32.bf16.bf16.f32 "
        "{%0,%1,%2,%3}, {%4,%5,%6,%7}, {%8,%9}, {%0,%1,%2,%3};\n"
        : "+f"(d[0]), "+f"(d[1]), "+f"(d[2]), "+f"(d[3])
        : "r"(a[0]), "r"(a[1]), "r"(a[2]), "r"(a[3]), "r"(b[0]), "r"(b[1]));
}
__device__ __forceinline__ float sigf(float x) {
    return __fdividef(1.f, 1.f + __expf(-x));
}
__device__ __forceinline__ float tanhf_(float x) {
    return 1.f - __fdividef(2.f, 1.f + __expf(2.f * x));
}

// ---------------------------------------------------------------------------
// Bounded sync primitives (raw spin first, nanosleep fallback, hard bound)
// ---------------------------------------------------------------------------
__device__ __forceinline__ void wait_prog_ge(int slot, unsigned int tgt) {
    if (threadIdx.x == 0) {
        bool ok = false;
        for (int it = 0; it < 4096; it++) {
            if (*(volatile unsigned int*)&g_prog[slot] >= tgt) { ok = true; break; }
        }
        if (!ok) {
            for (int it = 0; it < (1 << 18); it++) {
                if (*(volatile unsigned int*)&g_prog[slot] >= tgt) break;
                __nanosleep(64);
            }
        }
        __threadfence();
    }
    __syncthreads();
}

__device__ __forceinline__ void group_barrier_n(int slot, unsigned int n) {
    __syncthreads();
    if (threadIdx.x == 0) {
        __threadfence();
        unsigned int* cnt = &g_bcnt[slot * 32];
        unsigned int* gen = &g_bgen[slot * 32];
        unsigned int g = atomicAdd(gen, 0u);
        unsigned int arr = atomicAdd(cnt, 1u);
        if (arr == n - 1u) {
            *cnt = 0u;
            __threadfence();
            atomicAdd(gen, 1u);
        } else {
            bool ok = false;
            for (int it = 0; it < 4096; it++) {
                if (*(volatile unsigned int*)gen != g) { ok = true; break; }
            }
            if (!ok) {
                for (int it = 0; it < (1 << 18); it++) {
                    if (*(volatile unsigned int*)gen != g) break;
                    __nanosleep(64);
                }
            }
        }
        __threadfence();
    }
    __syncthreads();
}

// ---------------------------------------------------------------------------
// Consolidated conversion kernel (weights + biases + sync reset, one launch)
// ---------------------------------------------------------------------------
__device__ __forceinline__ void conv_one(const float* __restrict__ M,
                                         bf16* __restrict__ hi, bf16* __restrict__ lo,
                                         int idx, int K, int Hdim)
{
    int N = 4 * Hdim;
    int P = idx / K, k = idx - P * K;
    int n = (P & 3) * Hdim + (P >> 2);
    float v = M[(size_t)k * N + n];
    bf16 h = __float2bfloat16_rn(v);
    hi[idx] = h;
    lo[idx] = __float2bfloat16_rn(v - __bfloat162float(h));
}

__global__ void conv_all(const float* __restrict__ W0, const float* __restrict__ W1,
                         const float* __restrict__ W2, const float* __restrict__ U0,
                         const float* __restrict__ U1, const float* __restrict__ U2,
                         const float* __restrict__ b0, const float* __restrict__ b1,
                         const float* __restrict__ b2,
                         bf16* __restrict__ whi, bf16* __restrict__ wlo,
                         bf16* __restrict__ uhi, bf16* __restrict__ ulo,
                         float* __restrict__ bp0, float* __restrict__ bpP)
{
    int idx = blockIdx.x * blockDim.x + threadIdx.x;
    if (idx < 65536)        conv_one(W0, whi + WOFF0, wlo + WOFF0, idx, 64, 256);
    else if (idx < 327680)  conv_one(W1, whi + WOFF1, wlo + WOFF1, idx - 65536, 256, 256);
    else if (idx < 458752)  conv_one(W2, whi + WOFF2, wlo + WOFF2, idx - 327680, 256, 128);
    else if (idx < 720896)  conv_one(U0, uhi + UOFF0, ulo + UOFF0, idx - 458752, 256, 256);
    else if (idx < 983040)  conv_one(U1, uhi + UOFF1, ulo + UOFF1, idx - 720896, 256, 256);
    else if (idx < 1048576) conv_one(U2, uhi + UOFF2, ulo + UOFF2, idx - 983040, 128, 128);
    else {
        int i = idx - 1048576;
        if (i < 1024)       bp0[i] = b0[(i & 3) * 256 + (i >> 2)];
        else if (i < 2048)  { int P = i - 1024; bpP[P] = b1[(P & 3) * 256 + (P >> 2)]; }
        else if (i < 2560)  { int P = i - 2048; bpP[1024 + P] = b2[(P & 3) * 128 + (P >> 2)]; }
        else if (i < 2568)  g_prog[i - 2560] = 0;
        else if (i < 2952)  { int j = i - 2568; g_bcnt[j] = 0; g_bgen[j] = 0; }
    }
}

__global__ void conv_split(const float* __restrict__ in,
                           bf16* __restrict__ hi, bf16* __restrict__ lo, int n4)
{
    int i = blockIdx.x * blockDim.x + threadIdx.x;
    if (i >= n4) return;
    float4 v = ((const float4*)in)[i];
    union { bf16 b[4]; uint2 u; } H, L;
    H.b[0] = __float2bfloat16_rn(v.x);
    H.b[1] = __float2bfloat16_rn(v.y);
    H.b[2] = __float2bfloat16_rn(v.z);
    H.b[3] = __float2bfloat16_rn(v.w);
    L.b[0] = __float2bfloat16_rn(v.x - __bfloat162float(H.b[0]));
    L.b[1] = __float2bfloat16_rn(v.y - __bfloat162float(H.b[1]));
    L.b[2] = __float2bfloat16_rn(v.z - __bfloat162float(H.b[2]));
    L.b[3] = __float2bfloat16_rn(v.w - __bfloat162float(H.b[3]));
    ((uint2*)hi)[i] = H.u;
    ((uint2*)lo)[i] = L.u;
}

// ---------------------------------------------------------------------------
// mma.sync GEMM (proven): used only for layer-0 xW precompute (K=64)
// ---------------------------------------------------------------------------
#define TSTRIDE 72
#define GEMM_SMEM (4 * 128 * TSTRIDE * 2)

__global__ __launch_bounds__(256)
void mma_gemm(const bf16* __restrict__ Ahi, const bf16* __restrict__ Alo,
              const bf16* __restrict__ Bhi, const bf16* __restrict__ Blo,
              const float* __restrict__ bias, float* __restrict__ C, int K, int N)
{
    extern __shared__ bf16 sm[];
    bf16* sAhi = sm;
    bf16* sAlo = sm + 128 * TSTRIDE;
    bf16* sBhi = sm + 2 * 128 * TSTRIDE;
    bf16* sBlo = sm + 3 * 128 * TSTRIDE;
    const uint32_t uAhi = smem_u32(sAhi), uAlo = smem_u32(sAlo);
    const uint32_t uBhi = smem_u32(sBhi), uBlo = smem_u32(sBlo);

    const int tid = threadIdx.x;
    const int wid = tid >> 5, lane = tid & 31;
    const int warp_m = wid & 1, warp_n = wid >> 1;
    const int bm = blockIdx.y * 128, bn = blockIdx.x * 128;

    float acc[4][4][4];
#pragma unroll
    for (int mi = 0; mi < 4; mi++)
#pragma unroll
        for (int ni = 0; ni < 4; ni++)
#pragma unroll
            for (int f = 0; f < 4; f++) acc[mi][ni][f] = 0.f;

    const int r8  = lane & 7;
    const int grp = lane >> 3;
    const int aRowOff = ((grp & 1) ? 8 : 0) + r8;
    const int aColOff = (grp & 2) ? 8 : 0;
    const int bSel = grp & 1;

    const int nchunk = K >> 6;
    for (int c = 0; c < nchunk; c++) {
        const int k0g = c << 6;
#pragma unroll
        for (int i = 0; i < 4; i++) {
            int idx = tid + i * 256;
            int row = idx >> 3, seg = idx & 7;
            size_t ga = (size_t)(bm + row) * K + k0g + seg * 8;
            size_t gb = (size_t)(bn + row) * K + k0g + seg * 8;
            int so = row * TSTRIDE + seg * 8;
            *(uint4*)(sAhi + so) = *(const uint4*)&Ahi[ga];
            *(uint4*)(sAlo + so) = *(const uint4*)&Alo[ga];
            *(uint4*)(sBhi + so) = *(const uint4*)&Bhi[gb];
            *(uint4*)(sBlo + so) = *(const uint4*)&Blo[gb];
        }
        __syncthreads();

#pragma unroll
        for (int ks = 0; ks < 4; ks++) {
            const int k0 = ks * 16;
            uint32_t aHi[4][4], aLo[4][4], bHi[4][2], bLo[4][2];
#pragma unroll
            for (int mi = 0; mi < 4; mi++) {
                int row = warp_m * 64 + mi * 16 + aRowOff;
                uint32_t off = (uint32_t)(row * TSTRIDE + k0 + aColOff) * 2;
                ldsm_x4(aHi[mi], uAhi + off);
                ldsm_x4(aLo[mi], uAlo + off);
            }
#pragma unroll
            for (int ni = 0; ni < 4; ni++) {
                int row = warp_n * 32 + ni * 8 + r8;
                uint32_t off = (uint32_t)(row * TSTRIDE + k0 + bSel * 8) * 2;
                ldsm_x2(bHi[ni], uBhi + off);
                ldsm_x2(bLo[ni], uBlo + off);
            }
#pragma unroll
            for (int mi = 0; mi < 4; mi++)
#pragma unroll
                for (int ni = 0; ni < 4; ni++) {
                    mma_16816(acc[mi][ni], aHi[mi], bHi[ni]);
                    mma_16816(acc[mi][ni], aHi[mi], bLo[ni]);
                    mma_16816(acc[mi][ni], aLo[mi], bHi[ni]);
                }
        }
        __syncthreads();
    }

    const int tg = lane >> 2, tp = lane & 3;
#pragma unroll
    for (int mi = 0; mi < 4; mi++) {
#pragma unroll
        for (int ni = 0; ni < 4; ni++) {
            int col = bn + warp_n * 32 + ni * 8 + tp * 2;
            int row0 = bm + warp_m * 64 + mi * 16 + tg;
            float2 o0, o1;
            o0.x = acc[mi][ni][0] + bias[col];
            o0.y = acc[mi][ni][1] + bias[col + 1];
            o1.x = acc[mi][ni][2] + bias[col];
            o1.y = acc[mi][ni][3] + bias[col + 1];
            *(float2*)&C[(size_t)row0 * N + col] = o0;
            *(float2*)&C[(size_t)(row0 + 8) * N + col] = o1;
        }
    }
}

// ---------------------------------------------------------------------------
// Fused wavefront LSTM: 3 layers pipelined over t, 512 threads/CTA
// (16 warps = 4/SMSP for latency hiding; 4x4 warp grid, warp tile 16 x WN).
// ---------------------------------------------------------------------------
#define LTHREADS 512

template<int HDIM, int KIN, int UPCv, int GRPN>
__device__ void run_layer(int bb, int cb, int gslot, int pubslot, int waitslot,
    const bf16* __restrict__ Uthi, const bf16* __restrict__ Utlo,
    const bf16* __restrict__ Wthi, const bf16* __restrict__ Wtlo,
    const float* __restrict__ biasp, const float* __restrict__ xW,
    const bf16* __restrict__ Hin_hi, const bf16* __restrict__ Hin_lo,
    bf16* __restrict__ Hhi, bf16* __restrict__ Hlo)
{
    constexpr int K    = HDIM;
    constexpr int PC   = 4 * UPCv;
    constexpr int WN   = PC / 4;
    constexpr int NI   = WN / 8;
    constexpr int KSU  = K / 16;
    constexpr int KS2U = K + 8;
    constexpr int U4U  = K / 8;
    constexpr int KSW  = KIN / 16;
    constexpr int KS2W = KIN + 8;
    constexpr int U4W  = KIN / 8;
    constexpr int KS2M = (KS2W > KS2U) ? KS2W : KS2U;
    constexpr int STW  = UPCv / 2;

    extern __shared__ bf16 dyn[];
    bf16* sUhi  = dyn;                               // PC x KS2U
    bf16* sUlo  = sUhi + PC * KS2U;
    bf16* sWhi  = sUlo + PC * KS2U;                  // PC x KS2W (if KIN)
    bf16* sWlo  = sWhi + (KIN ? PC * KS2W : 0);
    bf16* sHs_hi = sWlo + (KIN ? PC * KS2W : 0);     // 64 x KS2M (A staging)
    bf16* sHs_lo = sHs_hi + 64 * KS2M;
    bf16* sSthi  = sHs_lo + 64 * KS2M;               // 64 x UPC stage-out
    bf16* sStlo  = sSthi + 64 * UPCv;
    const uint32_t uUhi = smem_u32(sUhi), uUlo = smem_u32(sUlo);
    const uint32_t uWhi = smem_u32(sWhi), uWlo = smem_u32(sWlo);
    const uint32_t uHhi = smem_u32(sHs_hi), uHlo = smem_u32(sHs_lo);

    const int tid = threadIdx.x;
    const int wid = tid >> 5, lane = tid & 31;
    const int wm = wid & 3, wn = wid >> 2;           // 4 x 4 warp grid
    const int b0 = bb * 64;

    const int r8  = lane & 7;
    const int grp = lane >> 3;
    const int aRowOff = ((grp & 1) ? 8 : 0) + r8;
    const int aColOff = (grp & 2) ? 8 : 0;
    const int bSel = grp & 1;
    const int tg = lane >> 2, tp = lane & 3;
    const bool evenp = (tp & 1) == 0;

    // Persistent U^T slice (packed rows cb*PC ..)
    for (int idx = tid; idx < PC * U4U; idx += LTHREADS) {
        int p = idx / U4U, q = idx - p * U4U;
        size_t g = (size_t)(cb * PC + p) * K + q * 8;
        *(uint4*)(sUhi + p * KS2U + q * 8) = *(const uint4*)&Uthi[g];
        *(uint4*)(sUlo + p * KS2U + q * 8) = *(const uint4*)&Utlo[g];
    }
    if constexpr (KIN > 0) {
        for (int idx = tid; idx < PC * U4W; idx += LTHREADS) {
            int p = idx / U4W, q = idx - p * U4W;
            size_t g = (size_t)(cb * PC + p) * KIN + q * 8;
            *(uint4*)(sWhi + p * KS2W + q * 8) = *(const uint4*)&Wthi[g];
            *(uint4*)(sWlo + p * KS2W + q * 8) = *(const uint4*)&Wtlo[g];
        }
    }
    __syncthreads();

    int colg[NI], uLoc[NI];
#pragma unroll
    for (int ni = 0; ni < NI; ni++) {
        int pcl = wn * WN + ni * 8 + 2 * tp;
        colg[ni] = cb * PC + pcl;
        uLoc[ni] = pcl >> 2;
    }
    float bs[NI][2];
    if constexpr (KIN > 0) {
#pragma unroll
        for (int ni = 0; ni < NI; ni++) {
            bs[ni][0] = biasp[colg[ni]];
            bs[ni][1] = biasp[colg[ni] + 1];
        }
    }

    float cst[NI][2];
#pragma unroll
    for (int ni = 0; ni < NI; ni++) { cst[ni][0] = 0.f; cst[ni][1] = 0.f; }

    const int rA = b0 + wm * 16 + tg;                // batch rows rA, rA+8
    float nxt[NI][4];
    if constexpr (KIN == 0) {
#pragma unroll
        for (int ni = 0; ni < NI; ni++) {
            float2 a = *(const float2*)&xW[((size_t)rA * TLEN) * (4 * HDIM) + colg[ni]];
            float2 b = *(const float2*)&xW[((size_t)(rA + 8) * TLEN) * (4 * HDIM) + colg[ni]];
            nxt[ni][0] = a.x; nxt[ni][1] = a.y; nxt[ni][2] = b.x; nxt[ni][3] = b.y;
        }
    }

    for (int t = 0; t < TLEN; t++) {
        float acc[NI][4];
#pragma unroll
        for (int ni = 0; ni < NI; ni++) {
            if constexpr (KIN == 0) {
                acc[ni][0] = nxt[ni][0]; acc[ni][1] = nxt[ni][1];
                acc[ni][2] = nxt[ni][2]; acc[ni][3] = nxt[ni][3];
            } else {
                acc[ni][0] = bs[ni][0]; acc[ni][1] = bs[ni][1];
                acc[ni][2] = bs[ni][0]; acc[ni][3] = bs[ni][1];
            }
        }

        // ---- Recurrent GEMM FIRST (own h(t-1) ready at round start) ----
        if (t > 0) {
            for (int idx = tid; idx < 64 * U4U; idx += LTHREADS) {
                int r = idx / U4U, q = idx - r * U4U;
                size_t g = ((size_t)(b0 + r) * TLEN + (t - 1)) * HDIM + q * 8;
                *(uint4*)(sHs_hi + r * KS2U + q * 8) = *(const uint4*)&Hhi[g];
                *(uint4*)(sHs_lo + r * KS2U + q * 8) = *(const uint4*)&Hlo[g];
            }
            __syncthreads();
#pragma unroll
            for (int ks = 0; ks < KSU; ks++) {
                uint32_t ahi[4], alo[4];
                uint32_t aoff = (uint32_t)((wm * 16 + aRowOff) * KS2U
                                           + ks * 16 + aColOff) * 2;
                ldsm_x4(ahi, uHhi + aoff);
                ldsm_x4(alo, uHlo + aoff);
#pragma unroll
                for (int ni = 0; ni < NI; ni++) {
                    uint32_t bh[2], bl[2];
                    uint32_t boff = (uint32_t)((wn * WN + ni * 8 + r8) * KS2U
                                               + ks * 16 + bSel * 8) * 2;
                    ldsm_x2(bh, uUhi + boff);
                    ldsm_x2(bl, uUlo + boff);
                    mma_16816(acc[ni], ahi, bh);
                    mma_16816(acc[ni], ahi, bl);
                    mma_16816(acc[ni], alo, bh);
                }
            }
            __syncthreads();   // sHs reads done before W-phase restages
        }

        // ---- Cross-layer wait + input GEMM (skew hidden under U-phase) ----
        if constexpr (KIN > 0) {
            wait_prog_ge(waitslot, (unsigned)(t + 1));
            for (int idx = tid; idx < 64 * U4W; idx += LTHREADS) {
                int r = idx / U4W, q = idx - r * U4W;
                size_t g = ((size_t)(b0 + r) * TLEN + t) * KIN + q * 8;
                *(uint4*)(sHs_hi + r * KS2W + q * 8) = *(const uint4*)&Hin_hi[g];
                *(uint4*)(sHs_lo + r * KS2W + q * 8) = *(const uint4*)&Hin_lo[g];
            }
            __syncthreads();
#pragma unroll
            for (int ks = 0; ks < KSW; ks++) {
                uint32_t ahi[4], alo[4];
                uint32_t aoff = (uint32_t)((wm * 16 + aRowOff) * KS2W
                                           + ks * 16 + aColOff) * 2;
                ldsm_x4(ahi, uHhi + aoff);
                ldsm_x4(alo, uHlo + aoff);
#pragma unroll
                for (int ni = 0; ni < NI; ni++) {
                    uint32_t bh[2], bl[2];
                    uint32_t boff = (uint32_t)((wn * WN + ni * 8 + r8) * KS2W
                                               + ks * 16 + bSel * 8) * 2;
                    ldsm_x2(bh, uWhi + boff);
                    ldsm_x2(bl, uWlo + boff);
                    mma_16816(acc[ni], ahi, bh);
                    mma_16816(acc[ni], ahi, bl);
                    mma_16816(acc[ni], alo, bh);
                }
            }
        }

        // Gates (even tp: i,f | odd tp: g,o of same unit); stage h out
#pragma unroll
        for (int ni = 0; ni < NI; ni++) {
            float v0, v1, v2, v3;
            if (evenp) {
                v0 = sigf(acc[ni][0]); v1 = sigf(acc[ni][1]);
                v2 = sigf(acc[ni][2]); v3 = sigf(acc[ni][3]);
            } else {
                v0 = tanhf_(acc[ni][0]); v1 = sigf(acc[ni][1]);
                v2 = tanhf_(acc[ni][2]); v3 = sigf(acc[ni][3]);
            }
            float p0 = __shfl_xor_sync(0xffffffffu, v0, 1);
            float p1 = __shfl_xor_sync(0xffffffffu, v1, 1);
            float p2 = __shfl_xor_sync(0xffffffffu, v2, 1);
            float p3 = __shfl_xor_sync(0xffffffffu, v3, 1);
            float i0 = evenp ? v0 : p0, f0 = evenp ? v1 : p1;
            float g0 = evenp ? p0 : v0, o0 = evenp ? p1 : v1;
            float i1 = evenp ? v2 : p2, f1 = evenp ? v3 : p3;
            float g1 = evenp ? p2 : v2, o1 = evenp ? p3 : v3;

            float c0 = fmaf(f0, cst[ni][0], i0 * g0);
            float c1 = fmaf(f1, cst[ni][1], i1 * g1);
            cst[ni][0] = c0;
            cst[ni][1] = c1;
            float h0 = o0 * tanhf_(c0);
            float h1 = o1 * tanhf_(c1);

            if (evenp) {
                int r0 = wm * 16 + tg, r1 = r0 + 8;
                bf16 h0h = __float2bfloat16_rn(h0);
                bf16 h1h = __float2bfloat16_rn(h1);
                sSthi[r0 * UPCv + uLoc[ni]] = h0h;
                sStlo[r0 * UPCv + uLoc[ni]] = __float2bfloat16_rn(h0 - __bfloat162float(h0h));
                sSthi[r1 * UPCv + uLoc[ni]] = h1h;
                sStlo[r1 * UPCv + uLoc[ni]] = __float2bfloat16_rn(h1 - __bfloat162float(h1h));
            }
        }

        // L0: prefetch next xW (hidden under store + barrier)
        if constexpr (KIN == 0) {
            if (t + 1 < TLEN) {
#pragma unroll
                for (int ni = 0; ni < NI; ni++) {
                    float2 a = *(const float2*)&xW[((size_t)rA * TLEN + t + 1) * (4 * HDIM) + colg[ni]];
                    float2 b = *(const float2*)&xW[((size_t)(rA + 8) * TLEN + t + 1) * (4 * HDIM) + colg[ni]];
                    nxt[ni][0] = a.x; nxt[ni][1] = a.y;
                    nxt[ni][2] = b.x; nxt[ni][3] = b.y;
                }
            }
        }

        __syncthreads();
        // Coalesced h store (hi & lo)
        for (int idx = tid; idx < 64 * STW; idx += LTHREADS) {
            int r = idx / STW, q = idx - r * STW;
            size_t g = ((size_t)(b0 + r) * TLEN + t) * HDIM + cb * UPCv + q * 2;
            *(uint32_t*)&Hhi[g] = ((const uint32_t*)sSthi)[r * STW + q];
            *(uint32_t*)&Hlo[g] = ((const uint32_t*)sStlo)[r * STW + q];
        }

        group_barrier_n(gslot, GRPN);
        if (pubslot >= 0 && cb == 0 && tid == 0)
            atomicExch(&g_prog[pubslot], (unsigned)(t + 1));
    }
}

__global__ __launch_bounds__(LTHREADS, 1) void fused_lstm()
{
    int bx = blockIdx.x;
    if (bx < 32) {
        int bb = bx >> 3, cb = bx & 7;
        run_layer<256, 0, 32, 8>(bb, cb, bb, bb, -1,
            g_Uthi + UOFF0, g_Utlo + UOFF0, nullptr, nullptr,
            nullptr, g_xW, nullptr, nullptr, g_H0hi, g_H0lo);
    } else if (bx < 96) {
        int l = bx - 32;
        int bb = l >> 4, cb = l & 15;
        run_layer<256, 256, 16, 16>(bb, cb, 4 + bb, 4 + bb, bb,
            g_Uthi + UOFF1, g_Utlo + UOFF1, g_Wthi + WOFF1, g_Wtlo + WOFF1,
            g_biasP, nullptr, g_H0hi, g_H0lo, g_H1hi, g_H1lo);
    } else {
        int l = bx - 96;
        int bb = l >> 3, cb = l & 7;
        run_layer<128, 256, 16, 8>(bb, cb, 8 + bb, -1, 4 + bb,
            g_Uthi + UOFF2, g_Utlo + UOFF2, g_Wthi + WOFF2, g_Wtlo + WOFF2,
            g_biasP + 1024, nullptr, g_H1hi, g_H1lo, g_H2hi, g_H2lo);
    }
}

// ---------------------------------------------------------------------------
// Final dense: out[b,d] = (hi+lo)[b,T-1,:128] @ Wd + bd
// ---------------------------------------------------------------------------
__global__ void dense_kernel(const float* __restrict__ Wd, const float* __restrict__ bd,
                             float* __restrict__ out)
{
    int b = blockIdx.x;
    int d = threadIdx.x;
    size_t base = ((size_t)b * TLEN + (TLEN - 1)) * 128;
    float acc = 0.f;
#pragma unroll 4
    for (int k = 0; k < 128; k++) {
        float h = __bfloat162float(g_H2hi[base + k]) + __bfloat162float(g_H2lo[base + k]);
        acc = fmaf(h, Wd[k * 64 + d], acc);
    }
    out[b * 64 + d] = acc + bd[d];
}

// ---------------------------------------------------------------------------
// Launch sequence: [0] conv_all  [1] conv_split  [2] mma_gemm
//                  [3] fused_lstm (ncu target)  [4] dense
// ---------------------------------------------------------------------------
#define FUSED_SMEM ((128 * 264 * 2 + 64 * 264 * 2 + 64 * 32 * 2) * 2)

extern "C" void kernel_launch(void* const* d_in, const int* in_sizes, int n_in,
                              void* d_out, int out_size)
{
    (void)in_sizes; (void)n_in; (void)out_size;
    const float* x  = (const float*)d_in[0];
    const float* W0 = (const float*)d_in[1];
    const float* U0 = (const float*)d_in[2];
    const float* b0 = (const float*)d_in[3];
    const float* W1 = (const float*)d_in[4];
    const float* U1 = (const float*)d_in[5];
    const float* b1 = (const float*)d_in[6];
    const float* W2 = (const float*)d_in[7];
    const float* U2 = (const float*)d_in[8];
    const float* b2 = (const float*)d_in[9];
    const float* Wd = (const float*)d_in[10];
    const float* bd = (const float*)d_in[11];
    float* out = (float*)d_out;

    void* p;
    cudaGetSymbolAddress(&p, g_xW);    float* xw = (float*)p;
    cudaGetSymbolAddress(&p, g_Ahi);   bf16* ahi = (bf16*)p;
    cudaGetSymbolAddress(&p, g_Alo);   bf16* alo = (bf16*)p;
    cudaGetSymbolAddress(&p, g_Wthi);  bf16* whi = (bf16*)p;
    cudaGetSymbolAddress(&p, g_Wtlo);  bf16* wlo = (bf16*)p;
    cudaGetSymbolAddress(&p, g_Uthi);  bf16* uhi = (bf16*)p;
    cudaGetSymbolAddress(&p, g_Utlo);  bf16* ulo = (bf16*)p;
    cudaGetSymbolAddress(&p, g_bias);  float* bp0 = (float*)p;
    cudaGetSymbolAddress(&p, g_biasP); float* bpP = (float*)p;

    cudaFuncSetAttribute(mma_gemm, cudaFuncAttributeMaxDynamicSharedMemorySize, GEMM_SMEM);
    cudaFuncSetAttribute(fused_lstm, cudaFuncAttributeMaxDynamicSharedMemorySize, FUSED_SMEM);

    // [0] all weight/bias conversion + sync reset (one launch)
    conv_all<<<4108, 256>>>(W0, W1, W2, U0, U1, U2, b0, b1, b2,
                            whi, wlo, uhi, ulo, bp0, bpP);
    // [1] x split
    conv_split<<<(MTOT * 64 / 4 + 255) / 256, 256>>>(x, ahi, alo, MTOT * 64 / 4);
    // [2] layer-0 xW precompute
    mma_gemm<<<dim3(8, MTOT / 128), 256, GEMM_SMEM>>>(ahi, alo, whi + WOFF0, wlo + WOFF0,
                                                      bp0, xw, 64, 1024);
    // [3] fused wavefront (profiling target)
    fused_lstm<<<128, LTHREADS, FUSED_SMEM>>>();
    // [4] dense head
    dense_kernel<<<BSZ, 64>>>(Wd, bd, out);
}

// round 14
// speedup vs baseline: 1.1715x; 1.1715x over previous
#include <cuda_runtime.h>
#include <cuda_bf16.h>
#include <cstdint>
#include <cstddef>

#define BSZ  256
#define TLEN 512
#define DIN  64
#define MTOT (BSZ * TLEN)

typedef __nv_bfloat16 bf16;

// ---------------------------------------------------------------------------
// Device-global scratch
// ---------------------------------------------------------------------------
__device__ float g_xW[MTOT * 1024];            // xW0 = x@W0 + b0, packed cols
__device__ bf16  g_Ahi[MTOT * 64];             // x split (layer-0 GEMM A)
__device__ bf16  g_Alo[MTOT * 64];
__device__ bf16  g_Wthi[458752];               // W^T packed (3 layers), hi
__device__ bf16  g_Wtlo[458752];
__device__ bf16  g_Uthi[589824];               // U^T packed (3 layers)
__device__ bf16  g_Utlo[589824];
__device__ float g_bias[1024];                 // packed b0 (for xW GEMM)
__device__ float g_biasP[1536];                // packed b1 [0:1024), b2 [1024:1536)
__device__ bf16  g_H0hi[MTOT * 256];           // h sequences (bf16 split)
__device__ bf16  g_H0lo[MTOT * 256];
__device__ bf16  g_H1hi[MTOT * 256];
__device__ bf16  g_H1lo[MTOT * 256];
__device__ bf16  g_H2hi[MTOT * 128];
__device__ bf16  g_H2lo[MTOT * 128];
__device__ unsigned int g_prog[8];             // [0..3]=L0 bb, [4..7]=L1 bb
__device__ unsigned int g_bcnt[12 * 32];       // 12 group-barrier slots, padded
__device__ unsigned int g_bgen[12 * 32];

#define WOFF0 0
#define WOFF1 (1024 * 64)
#define WOFF2 (1024 * 64 + 1024 * 256)
#define UOFF0 0
#define UOFF1 (1024 * 256)
#define UOFF2 (2 * 1024 * 256)

// ---------------------------------------------------------------------------
// sm_100-safe helpers (ldmatrix + mma.sync; no tcgen05)
// ---------------------------------------------------------------------------
__device__ __forceinline__ uint32_t smem_u32(const void* p) {
    uint32_t a;
    asm("{ .reg .u64 t; cvta.to.shared.u64 t, %1; cvt.u32.u64 %0, t; }"
        : "=r"(a) : "l"(p));
    return a;
}
__device__ __forceinline__ void ldsm_x4(uint32_t* r, uint32_t addr) {
    asm volatile("ldmatrix.sync.aligned.m8n8.x4.shared.b16 {%0,%1,%2,%3}, [%4];"
                 : "=r"(r[0]), "=r"(r[1]), "=r"(r[2]), "=r"(r[3]) : "r"(addr));
}
__device__ __forceinline__ void mma_16816(float* d, const uint32_t* a, const uint32_t* b) {
    asm volatile(
        "mma.sync.aligned.m16n8k16.row.col.f32.bf16.bf16.f32 "
        "{%0,%1,%2,%3}, {%4,%5,%6,%7}, {%8,%9}, {%0,%1,%2,%3};\n"
        : "+f"(d[0]), "+f"(d[1]), "+f"(d[2]), "+f"(d[3])
        : "r"(a[0]), "r"(a[1]), "r"(a[2]), "r"(a[3]), "r"(b[0]), "r"(b[1]));
}
__device__ __forceinline__ float sigf(float x) {
    return __fdividef(1.f, 1.f + __expf(-x));
}
__device__ __forceinline__ float tanhf_(float x) {
    return 1.f - __fdividef(2.f, 1.f + __expf(2.f * x));
}

// ---------------------------------------------------------------------------
// Bounded sync primitives (raw spin first, nanosleep fallback, hard bound)
// ---------------------------------------------------------------------------
__device__ __forceinline__ void wait_prog_ge(int slot, unsigned int tgt) {
    if (threadIdx.x == 0) {
        bool ok = false;
        for (int it = 0; it < 4096; it++) {
            if (*(volatile unsigned int*)&g_prog[slot] >= tgt) { ok = true; break; }
        }
        if (!ok) {
            for (int it = 0; it < (1 << 18); it++) {
                if (*(volatile unsigned int*)&g_prog[slot] >= tgt) break;
                __nanosleep(64);
            }
        }
        __threadfence();
    }
    __syncthreads();
}

__device__ __forceinline__ void group_barrier_n(int slot, unsigned int n) {
    __syncthreads();
    if (threadIdx.x == 0) {
        __threadfence();
        unsigned int* cnt = &g_bcnt[slot * 32];
        unsigned int* gen = &g_bgen[slot * 32];
        unsigned int g = atomicAdd(gen, 0u);
        unsigned int arr = atomicAdd(cnt, 1u);
        if (arr == n - 1u) {
            *cnt = 0u;
            __threadfence();
            atomicAdd(gen, 1u);
        } else {
            bool ok = false;
            for (int it = 0; it < 4096; it++) {
                if (*(volatile unsigned int*)gen != g) { ok = true; break; }
            }
            if (!ok) {
                for (int it = 0; it < (1 << 18); it++) {
                    if (*(volatile unsigned int*)gen != g) break;
                    __nanosleep(64);
                }
            }
        }
        __threadfence();
    }
    __syncthreads();
}

// ---------------------------------------------------------------------------
// Consolidated conversion kernel (weights + biases + sync reset, one launch)
// ---------------------------------------------------------------------------
__device__ __forceinline__ void conv_one(const float* __restrict__ M,
                                         bf16* __restrict__ hi, bf16* __restrict__ lo,
                                         int idx, int K, int Hdim)
{
    int N = 4 * Hdim;
    int P = idx / K, k = idx - P * K;
    int n = (P & 3) * Hdim + (P >> 2);
    float v = M[(size_t)k * N + n];
    bf16 h = __float2bfloat16_rn(v);
    hi[idx] = h;
    lo[idx] = __float2bfloat16_rn(v - __bfloat162float(h));
}

__global__ void conv_all(const float* __restrict__ W0, const float* __restrict__ W1,
                         const float* __restrict__ W2, const float* __restrict__ U0,
                         const float* __restrict__ U1, const float* __restrict__ U2,
                         const float* __restrict__ b0, const float* __restrict__ b1,
                         const float* __restrict__ b2,
                         bf16* __restrict__ whi, bf16* __restrict__ wlo,
                         bf16* __restrict__ uhi, bf16* __restrict__ ulo,
                         float* __restrict__ bp0, float* __restrict__ bpP)
{
    int idx = blockIdx.x * blockDim.x + threadIdx.x;
    if (idx < 65536)        conv_one(W0, whi + WOFF0, wlo + WOFF0, idx, 64, 256);
    else if (idx < 327680)  conv_one(W1, whi + WOFF1, wlo + WOFF1, idx - 65536, 256, 256);
    else if (idx < 458752)  conv_one(W2, whi + WOFF2, wlo + WOFF2, idx - 327680, 256, 128);
    else if (idx < 720896)  conv_one(U0, uhi + UOFF0, ulo + UOFF0, idx - 458752, 256, 256);
    else if (idx < 983040)  conv_one(U1, uhi + UOFF1, ulo + UOFF1, idx - 720896, 256, 256);
    else if (idx < 1048576) conv_one(U2, uhi + UOFF2, ulo + UOFF2, idx - 983040, 128, 128);
    else {
        int i = idx - 1048576;
        if (i < 1024)       bp0[i] = b0[(i & 3) * 256 + (i >> 2)];
        else if (i < 2048)  { int P = i - 1024; bpP[P] = b1[(P & 3) * 256 + (P >> 2)]; }
        else if (i < 2560)  { int P = i - 2048; bpP[1024 + P] = b2[(P & 3) * 128 + (P >> 2)]; }
        else if (i < 2568)  g_prog[i - 2560] = 0;
        else if (i < 2952)  { int j = i - 2568; g_bcnt[j] = 0; g_bgen[j] = 0; }
    }
}

__global__ void conv_split(const float* __restrict__ in,
                           bf16* __restrict__ hi, bf16* __restrict__ lo, int n4)
{
    int i = blockIdx.x * blockDim.x + threadIdx.x;
    if (i >= n4) return;
    float4 v = ((const float4*)in)[i];
    union { bf16 b[4]; uint2 u; } H, L;
    H.b[0] = __float2bfloat16_rn(v.x);
    H.b[1] = __float2bfloat16_rn(v.y);
    H.b[2] = __float2bfloat16_rn(v.z);
    H.b[3] = __float2bfloat16_rn(v.w);
    L.b[0] = __float2bfloat16_rn(v.x - __bfloat162float(H.b[0]));
    L.b[1] = __float2bfloat16_rn(v.y - __bfloat162float(H.b[1]));
    L.b[2] = __float2bfloat16_rn(v.z - __bfloat162float(H.b[2]));
    L.b[3] = __float2bfloat16_rn(v.w - __bfloat162float(H.b[3]));
    ((uint2*)hi)[i] = H.u;
    ((uint2*)lo)[i] = L.u;
}

// ---------------------------------------------------------------------------
// mma.sync GEMM (proven): used only for layer-0 xW precompute (K=64)
// ---------------------------------------------------------------------------
#define TSTRIDE 72
#define GEMM_SMEM (4 * 128 * TSTRIDE * 2)

__global__ __launch_bounds__(256)
void mma_gemm(const bf16* __restrict__ Ahi, const bf16* __restrict__ Alo,
              const bf16* __restrict__ Bhi, const bf16* __restrict__ Blo,
              const float* __restrict__ bias, float* __restrict__ C, int K, int N)
{
    extern __shared__ bf16 sm[];
    bf16* sAhi = sm;
    bf16* sAlo = sm + 128 * TSTRIDE;
    bf16* sBhi = sm + 2 * 128 * TSTRIDE;
    bf16* sBlo = sm + 3 * 128 * TSTRIDE;
    const uint32_t uAhi = smem_u32(sAhi), uAlo = smem_u32(sAlo);
    const uint32_t uBhi = smem_u32(sBhi), uBlo = smem_u32(sBlo);

    const int tid = threadIdx.x;
    const int wid = tid >> 5, lane = tid & 31;
    const int warp_m = wid & 1, warp_n = wid >> 1;
    const int bm = blockIdx.y * 128, bn = blockIdx.x * 128;

    float acc[4][4][4];
#pragma unroll
    for (int mi = 0; mi < 4; mi++)
#pragma unroll
        for (int ni = 0; ni < 4; ni++)
#pragma unroll
            for (int f = 0; f < 4; f++) acc[mi][ni][f] = 0.f;

    const int r8  = lane & 7;
    const int grp = lane >> 3;
    const int aRowOff = ((grp & 1) ? 8 : 0) + r8;
    const int aColOff = (grp & 2) ? 8 : 0;
    // B merged hi/lo ldsm_x4: lanes 0-15 -> hi array, 16-31 -> lo array
    const int bK8 = (grp & 1) * 8;

    const int nchunk = K >> 6;
    for (int c = 0; c < nchunk; c++) {
        const int k0g = c << 6;
#pragma unroll
        for (int i = 0; i < 4; i++) {
            int idx = tid + i * 256;
            int row = idx >> 3, seg = idx & 7;
            size_t ga = (size_t)(bm + row) * K + k0g + seg * 8;
            size_t gb = (size_t)(bn + row) * K + k0g + seg * 8;
            int so = row * TSTRIDE + seg * 8;
            *(uint4*)(sAhi + so) = *(const uint4*)&Ahi[ga];
            *(uint4*)(sAlo + so) = *(const uint4*)&Alo[ga];
            *(uint4*)(sBhi + so) = *(const uint4*)&Bhi[gb];
            *(uint4*)(sBlo + so) = *(const uint4*)&Blo[gb];
        }
        __syncthreads();

#pragma unroll
        for (int ks = 0; ks < 4; ks++) {
            const int k0 = ks * 16;
            uint32_t aHi[4][4], aLo[4][4], bHL[4][4];
#pragma unroll
            for (int mi = 0; mi < 4; mi++) {
                int row = warp_m * 64 + mi * 16 + aRowOff;
                uint32_t off = (uint32_t)(row * TSTRIDE + k0 + aColOff) * 2;
                ldsm_x4(aHi[mi], uAhi + off);
                ldsm_x4(aLo[mi], uAlo + off);
            }
#pragma unroll
            for (int ni = 0; ni < 4; ni++) {
                int row = warp_n * 32 + ni * 8 + r8;
                uint32_t off = (uint32_t)(row * TSTRIDE + k0 + bK8) * 2;
                uint32_t base = (grp & 2) ? uBlo : uBhi;
                ldsm_x4(bHL[ni], base + off);
            }
#pragma unroll
            for (int mi = 0; mi < 4; mi++)
#pragma unroll
                for (int ni = 0; ni < 4; ni++) {
                    mma_16816(acc[mi][ni], aHi[mi], bHL[ni] + 0);
                    mma_16816(acc[mi][ni], aHi[mi], bHL[ni] + 2);
                    mma_16816(acc[mi][ni], aLo[mi], bHL[ni] + 0);
                }
        }
        __syncthreads();
    }

    const int tg = lane >> 2, tp = lane & 3;
#pragma unroll
    for (int mi = 0; mi < 4; mi++) {
#pragma unroll
        for (int ni = 0; ni < 4; ni++) {
            int col = bn + warp_n * 32 + ni * 8 + tp * 2;
            int row0 = bm + warp_m * 64 + mi * 16 + tg;
            float2 o0, o1;
            o0.x = acc[mi][ni][0] + bias[col];
            o0.y = acc[mi][ni][1] + bias[col + 1];
            o1.x = acc[mi][ni][2] + bias[col];
            o1.y = acc[mi][ni][3] + bias[col + 1];
            *(float2*)&C[(size_t)row0 * N + col] = o0;
            *(float2*)&C[(size_t)(row0 + 8) * N + col] = o1;
        }
    }
}

// ---------------------------------------------------------------------------
// Fused wavefront LSTM (R12 structure, 256 threads): B hi/lo fragments fetched
// by ONE ldsm_x4 (lanes 0-15 address hi, 16-31 address lo) -> 33% fewer LDSM.
// ---------------------------------------------------------------------------
template<int HDIM, int KIN, int UPCv, int GRPN>
__device__ void run_layer(int bb, int cb, int gslot, int pubslot, int waitslot,
    const bf16* __restrict__ Uthi, const bf16* __restrict__ Utlo,
    const bf16* __restrict__ Wthi, const bf16* __restrict__ Wtlo,
    const float* __restrict__ biasp, const float* __restrict__ xW,
    const bf16* __restrict__ Hin_hi, const bf16* __restrict__ Hin_lo,
    bf16* __restrict__ Hhi, bf16* __restrict__ Hlo)
{
    constexpr int K    = HDIM;
    constexpr int PC   = 4 * UPCv;
    constexpr int WN   = PC / 4;
    constexpr int NI   = WN / 8;
    constexpr int KSU  = K / 16;
    constexpr int KS2U = K + 8;
    constexpr int U4U  = K / 8;
    constexpr int KSW  = KIN / 16;
    constexpr int KS2W = KIN + 8;
    constexpr int U4W  = KIN / 8;
    constexpr int KS2M = (KS2W > KS2U) ? KS2W : KS2U;
    constexpr int STW  = UPCv / 2;

    extern __shared__ bf16 dyn[];
    bf16* sUhi  = dyn;                               // PC x KS2U
    bf16* sUlo  = sUhi + PC * KS2U;
    bf16* sWhi  = sUlo + PC * KS2U;                  // PC x KS2W (if KIN)
    bf16* sWlo  = sWhi + (KIN ? PC * KS2W : 0);
    bf16* sHs_hi = sWlo + (KIN ? PC * KS2W : 0);     // 64 x KS2M (A staging)
    bf16* sHs_lo = sHs_hi + 64 * KS2M;
    bf16* sSthi  = sHs_lo + 64 * KS2M;               // 64 x UPC stage-out
    bf16* sStlo  = sSthi + 64 * UPCv;
    const uint32_t uUhi = smem_u32(sUhi), uUlo = smem_u32(sUlo);
    const uint32_t uWhi = smem_u32(sWhi), uWlo = smem_u32(sWlo);
    const uint32_t uHhi = smem_u32(sHs_hi), uHlo = smem_u32(sHs_lo);

    const int tid = threadIdx.x;
    const int wid = tid >> 5, lane = tid & 31;
    const int wm = wid & 1, wn = wid >> 1;
    const int b0 = bb * 64;

    const int r8  = lane & 7;
    const int grp = lane >> 3;
    const int aRowOff = ((grp & 1) ? 8 : 0) + r8;
    const int aColOff = (grp & 2) ? 8 : 0;
    const int bK8 = (grp & 1) * 8;                   // k-half select
    const bool bLoHalf = (grp & 2) != 0;             // lanes 16-31 -> lo array
    const int tg = lane >> 2, tp = lane & 3;
    const bool evenp = (tp & 1) == 0;

    // Persistent U^T slice (packed rows cb*PC ..)
    for (int idx = tid; idx < PC * U4U; idx += 256) {
        int p = idx / U4U, q = idx - p * U4U;
        size_t g = (size_t)(cb * PC + p) * K + q * 8;
        *(uint4*)(sUhi + p * KS2U + q * 8) = *(const uint4*)&Uthi[g];
        *(uint4*)(sUlo + p * KS2U + q * 8) = *(const uint4*)&Utlo[g];
    }
    if constexpr (KIN > 0) {
        for (int idx = tid; idx < PC * U4W; idx += 256) {
            int p = idx / U4W, q = idx - p * U4W;
            size_t g = (size_t)(cb * PC + p) * KIN + q * 8;
            *(uint4*)(sWhi + p * KS2W + q * 8) = *(const uint4*)&Wthi[g];
            *(uint4*)(sWlo + p * KS2W + q * 8) = *(const uint4*)&Wtlo[g];
        }
    }
    __syncthreads();

    const uint32_t uBU = bLoHalf ? uUlo : uUhi;      // per-lane B base (U phase)
    const uint32_t uBW = bLoHalf ? uWlo : uWhi;      // per-lane B base (W phase)

    int colg[NI], uLoc[NI];
#pragma unroll
    for (int ni = 0; ni < NI; ni++) {
        int pcl = wn * WN + ni * 8 + 2 * tp;
        colg[ni] = cb * PC + pcl;
        uLoc[ni] = pcl >> 2;
    }
    float bs[NI][2];
    if constexpr (KIN > 0) {
#pragma unroll
        for (int ni = 0; ni < NI; ni++) {
            bs[ni][0] = biasp[colg[ni]];
            bs[ni][1] = biasp[colg[ni] + 1];
        }
    }

    float cst[2][NI][2];
#pragma unroll
    for (int mi = 0; mi < 2; mi++)
#pragma unroll
        for (int ni = 0; ni < NI; ni++) { cst[mi][ni][0] = 0.f; cst[mi][ni][1] = 0.f; }

    float nxt[2][NI][4];
    if constexpr (KIN == 0) {
#pragma unroll
        for (int mi = 0; mi < 2; mi++) {
            size_t row = (size_t)(b0 + wm * 32 + mi * 16 + tg);
#pragma unroll
            for (int ni = 0; ni < NI; ni++) {
                float2 a = *(const float2*)&xW[(row * TLEN) * (4 * HDIM) + colg[ni]];
                float2 b = *(const float2*)&xW[((row + 8) * TLEN) * (4 * HDIM) + colg[ni]];
                nxt[mi][ni][0] = a.x; nxt[mi][ni][1] = a.y;
                nxt[mi][ni][2] = b.x; nxt[mi][ni][3] = b.y;
            }
        }
    }

    for (int t = 0; t < TLEN; t++) {
        float acc[2][NI][4];
#pragma unroll
        for (int mi = 0; mi < 2; mi++)
#pragma unroll
            for (int ni = 0; ni < NI; ni++) {
                if constexpr (KIN == 0) {
                    acc[mi][ni][0] = nxt[mi][ni][0]; acc[mi][ni][1] = nxt[mi][ni][1];
                    acc[mi][ni][2] = nxt[mi][ni][2]; acc[mi][ni][3] = nxt[mi][ni][3];
                } else {
                    acc[mi][ni][0] = bs[ni][0]; acc[mi][ni][1] = bs[ni][1];
                    acc[mi][ni][2] = bs[ni][0]; acc[mi][ni][3] = bs[ni][1];
                }
            }

        // ---- Recurrent GEMM FIRST (own h(t-1) ready at round start) ----
        if (t > 0) {
            for (int idx = tid; idx < 64 * U4U; idx += 256) {
                int r = idx / U4U, q = idx - r * U4U;
                size_t g = ((size_t)(b0 + r) * TLEN + (t - 1)) * HDIM + q * 8;
                *(uint4*)(sHs_hi + r * KS2U + q * 8) = *(const uint4*)&Hhi[g];
                *(uint4*)(sHs_lo + r * KS2U + q * 8) = *(const uint4*)&Hlo[g];
            }
            __syncthreads();
#pragma unroll
            for (int ks = 0; ks < KSU; ks++) {
                uint32_t ahi[2][4], alo[2][4];
#pragma unroll
                for (int mi = 0; mi < 2; mi++) {
                    uint32_t aoff = (uint32_t)((wm * 32 + mi * 16 + aRowOff) * KS2U
                                               + ks * 16 + aColOff) * 2;
                    ldsm_x4(ahi[mi], uHhi + aoff);
                    ldsm_x4(alo[mi], uHlo + aoff);
                }
#pragma unroll
                for (int ni = 0; ni < NI; ni++) {
                    uint32_t bhl[4];
                    uint32_t boff = (uint32_t)((wn * WN + ni * 8 + r8) * KS2U
                                               + ks * 16 + bK8) * 2;
                    ldsm_x4(bhl, uBU + boff);
#pragma unroll
                    for (int mi = 0; mi < 2; mi++) {
                        mma_16816(acc[mi][ni], ahi[mi], bhl + 0);
                        mma_16816(acc[mi][ni], ahi[mi], bhl + 2);
                        mma_16816(acc[mi][ni], alo[mi], bhl + 0);
                    }
                }
            }
            __syncthreads();   // sHs reads done before W-phase restages
        }

        // ---- Cross-layer wait + input GEMM (skew hidden under U-phase) ----
        if constexpr (KIN > 0) {
            wait_prog_ge(waitslot, (unsigned)(t + 1));
            for (int idx = tid; idx < 64 * U4W; idx += 256) {
                int r = idx / U4W, q = idx - r * U4W;
                size_t g = ((size_t)(b0 + r) * TLEN + t) * KIN + q * 8;
                *(uint4*)(sHs_hi + r * KS2W + q * 8) = *(const uint4*)&Hin_hi[g];
                *(uint4*)(sHs_lo + r * KS2W + q * 8) = *(const uint4*)&Hin_lo[g];
            }
            __syncthreads();
#pragma unroll
            for (int ks = 0; ks < KSW; ks++) {
                uint32_t ahi[2][4], alo[2][4];
#pragma unroll
                for (int mi = 0; mi < 2; mi++) {
                    uint32_t aoff = (uint32_t)((wm * 32 + mi * 16 + aRowOff) * KS2W
                                               + ks * 16 + aColOff) * 2;
                    ldsm_x4(ahi[mi], uHhi + aoff);
                    ldsm_x4(alo[mi], uHlo + aoff);
                }
#pragma unroll
                for (int ni = 0; ni < NI; ni++) {
                    uint32_t bhl[4];
                    uint32_t boff = (uint32_t)((wn * WN + ni * 8 + r8) * KS2W
                                               + ks * 16 + bK8) * 2;
                    ldsm_x4(bhl, uBW + boff);
#pragma unroll
                    for (int mi = 0; mi < 2; mi++) {
                        mma_16816(acc[mi][ni], ahi[mi], bhl + 0);
                        mma_16816(acc[mi][ni], ahi[mi], bhl + 2);
                        mma_16816(acc[mi][ni], alo[mi], bhl + 0);
                    }
                }
            }
        }

        // Gates (even tp: i,f | odd tp: g,o of same unit); stage h out
#pragma unroll
        for (int mi = 0; mi < 2; mi++) {
#pragma unroll
            for (int ni = 0; ni < NI; ni++) {
                float v0, v1, v2, v3;
                if (evenp) {
                    v0 = sigf(acc[mi][ni][0]); v1 = sigf(acc[mi][ni][1]);
                    v2 = sigf(acc[mi][ni][2]); v3 = sigf(acc[mi][ni][3]);
                } else {
                    v0 = tanhf_(acc[mi][ni][0]); v1 = sigf(acc[mi][ni][1]);
                    v2 = tanhf_(acc[mi][ni][2]); v3 = sigf(acc[mi][ni][3]);
                }
                float p0 = __shfl_xor_sync(0xffffffffu, v0, 1);
                float p1 = __shfl_xor_sync(0xffffffffu, v1, 1);
                float p2 = __shfl_xor_sync(0xffffffffu, v2, 1);
                float p3 = __shfl_xor_sync(0xffffffffu, v3, 1);
                float i0 = evenp ? v0 : p0, f0 = evenp ? v1 : p1;
                float g0 = evenp ? p0 : v0, o0 = evenp ? p1 : v1;
                float i1 = evenp ? v2 : p2, f1 = evenp ? v3 : p3;
                float g1 = evenp ? p2 : v2, o1 = evenp ? p3 : v3;

                float c0 = fmaf(f0, cst[mi][ni][0], i0 * g0);
                float c1 = fmaf(f1, cst[mi][ni][1], i1 * g1);
                cst[mi][ni][0] = c0;
                cst[mi][ni][1] = c1;
                float h0 = o0 * tanhf_(c0);
                float h1 = o1 * tanhf_(c1);

                if (evenp) {
                    int r0 = wm * 32 + mi * 16 + tg, r1 = r0 + 8;
                    bf16 h0h = __float2bfloat16_rn(h0);
                    bf16 h1h = __float2bfloat16_rn(h1);
                    sSthi[r0 * UPCv + uLoc[ni]] = h0h;
                    sStlo[r0 * UPCv + uLoc[ni]] = __float2bfloat16_rn(h0 - __bfloat162float(h0h));
                    sSthi[r1 * UPCv + uLoc[ni]] = h1h;
                    sStlo[r1 * UPCv + uLoc[ni]] = __float2bfloat16_rn(h1 - __bfloat162float(h1h));
                }
            }
        }

        // L0: prefetch next xW (hidden under store + barrier)
        if constexpr (KIN == 0) {
            if (t + 1 < TLEN) {
#pragma unroll
                for (int mi = 0; mi < 2; mi++) {
                    size_t row = (size_t)(b0 + wm * 32 + mi * 16 + tg);
#pragma unroll
                    for (int ni = 0; ni < NI; ni++) {
                        float2 a = *(const float2*)&xW[(row * TLEN + t + 1) * (4 * HDIM) + colg[ni]];
                        float2 b = *(const float2*)&xW[((row + 8) * TLEN + t + 1) * (4 * HDIM) + colg[ni]];
                        nxt[mi][ni][0] = a.x; nxt[mi][ni][1] = a.y;
                        nxt[mi][ni][2] = b.x; nxt[mi][ni][3] = b.y;
                    }
                }
            }
        }

        __syncthreads();
        // Coalesced h store (hi & lo)
        for (int idx = tid; idx < 64 * STW; idx += 256) {
            int r = idx / STW, q = idx - r * STW;
            size_t g = ((size_t)(b0 + r) * TLEN + t) * HDIM + cb * UPCv + q * 2;
            *(uint32_t*)&Hhi[g] = ((const uint32_t*)sSthi)[r * STW + q];
            *(uint32_t*)&Hlo[g] = ((const uint32_t*)sStlo)[r * STW + q];
        }

        group_barrier_n(gslot, GRPN);
        if (pubslot >= 0 && cb == 0 && tid == 0)
            atomicExch(&g_prog[pubslot], (unsigned)(t + 1));
    }
}

__global__ __launch_bounds__(256, 1) void fused_lstm()
{
    int bx = blockIdx.x;
    if (bx < 32) {
        int bb = bx >> 3, cb = bx & 7;
        run_layer<256, 0, 32, 8>(bb, cb, bb, bb, -1,
            g_Uthi + UOFF0, g_Utlo + UOFF0, nullptr, nullptr,
            nullptr, g_xW, nullptr, nullptr, g_H0hi, g_H0lo);
    } else if (bx < 96) {
        int l = bx - 32;
        int bb = l >> 4, cb = l & 15;
        run_layer<256, 256, 16, 16>(bb, cb, 4 + bb, 4 + bb, bb,
            g_Uthi + UOFF1, g_Utlo + UOFF1, g_Wthi + WOFF1, g_Wtlo + WOFF1,
            g_biasP, nullptr, g_H0hi, g_H0lo, g_H1hi, g_H1lo);
    } else {
        int l = bx - 96;
        int bb = l >> 3, cb = l & 7;
        run_layer<128, 256, 16, 8>(bb, cb, 8 + bb, -1, 4 + bb,
            g_Uthi + UOFF2, g_Utlo + UOFF2, g_Wthi + WOFF2, g_Wtlo + WOFF2,
            g_biasP + 1024, nullptr, g_H1hi, g_H1lo, g_H2hi, g_H2lo);
    }
}

// ---------------------------------------------------------------------------
// Final dense: out[b,d] = (hi+lo)[b,T-1,:128] @ Wd + bd
// ---------------------------------------------------------------------------
__global__ void dense_kernel(const float* __restrict__ Wd, const float* __restrict__ bd,
                             float* __restrict__ out)
{
    int b = blockIdx.x;
    int d = threadIdx.x;
    size_t base = ((size_t)b * TLEN + (TLEN - 1)) * 128;
    float acc = 0.f;
#pragma unroll 4
    for (int k = 0; k < 128; k++) {
        float h = __bfloat162float(g_H2hi[base + k]) + __bfloat162float(g_H2lo[base + k]);
        acc = fmaf(h, Wd[k * 64 + d], acc);
    }
    out[b * 64 + d] = acc + bd[d];
}

// ---------------------------------------------------------------------------
// Launch sequence: [0] conv_all  [1] conv_split  [2] mma_gemm
//                  [3] fused_lstm (ncu target)  [4] dense
// ---------------------------------------------------------------------------
#define FUSED_SMEM ((128 * 264 * 2 + 64 * 264 * 2 + 64 * 32 * 2) * 2)

extern "C" void kernel_launch(void* const* d_in, const int* in_sizes, int n_in,
                              void* d_out, int out_size)
{
    (void)in_sizes; (void)n_in; (void)out_size;
    const float* x  = (const float*)d_in[0];
    const float* W0 = (const float*)d_in[1];
    const float* U0 = (const float*)d_in[2];
    const float* b0 = (const float*)d_in[3];
    const float* W1 = (const float*)d_in[4];
    const float* U1 = (const float*)d_in[5];
    const float* b1 = (const float*)d_in[6];
    const float* W2 = (const float*)d_in[7];
    const float* U2 = (const float*)d_in[8];
    const float* b2 = (const float*)d_in[9];
    const float* Wd = (const float*)d_in[10];
    const float* bd = (const float*)d_in[11];
    float* out = (float*)d_out;

    void* p;
    cudaGetSymbolAddress(&p, g_xW);    float* xw = (float*)p;
    cudaGetSymbolAddress(&p, g_Ahi);   bf16* ahi = (bf16*)p;
    cudaGetSymbolAddress(&p, g_Alo);   bf16* alo = (bf16*)p;
    cudaGetSymbolAddress(&p, g_Wthi);  bf16* whi = (bf16*)p;
    cudaGetSymbolAddress(&p, g_Wtlo);  bf16* wlo = (bf16*)p;
    cudaGetSymbolAddress(&p, g_Uthi);  bf16* uhi = (bf16*)p;
    cudaGetSymbolAddress(&p, g_Utlo);  bf16* ulo = (bf16*)p;
    cudaGetSymbolAddress(&p, g_bias);  float* bp0 = (float*)p;
    cudaGetSymbolAddress(&p, g_biasP); float* bpP = (float*)p;

    cudaFuncSetAttribute(mma_gemm, cudaFuncAttributeMaxDynamicSharedMemorySize, GEMM_SMEM);
    cudaFuncSetAttribute(fused_lstm, cudaFuncAttributeMaxDynamicSharedMemorySize, FUSED_SMEM);

    // [0] all weight/bias conversion + sync reset (one launch)
    conv_all<<<4108, 256>>>(W0, W1, W2, U0, U1, U2, b0, b1, b2,
                            whi, wlo, uhi, ulo, bp0, bpP);
    // [1] x split
    conv_split<<<(MTOT * 64 / 4 + 255) / 256, 256>>>(x, ahi, alo, MTOT * 64 / 4);
    // [2] layer-0 xW precompute
    mma_gemm<<<dim3(8, MTOT / 128), 256, GEMM_SMEM>>>(ahi, alo, whi + WOFF0, wlo + WOFF0,
                                                      bp0, xw, 64, 1024);
    // [3] fused wavefront (profiling target)
    fused_lstm<<<128, 256, FUSED_SMEM>>>();
    // [4] dense head
    dense_kernel<<<BSZ, 64>>>(Wd, bd, out);
}

// round 15
// speedup vs baseline: 1.2541x; 1.0705x over previous
#include <cuda_runtime.h>
#include <cuda_bf16.h>
#include <cstdint>
#include <cstddef>

#define BSZ  256
#define TLEN 512
#define DIN  64
#define MTOT (BSZ * TLEN)

typedef __nv_bfloat16 bf16;

// ---------------------------------------------------------------------------
// Device-global scratch
// ---------------------------------------------------------------------------
__device__ float g_xW[MTOT * 1024];            // xW0 = x@W0 + b0, packed cols
__device__ bf16  g_Ahi[MTOT * 64];             // x split (layer-0 GEMM A)
__device__ bf16  g_Alo[MTOT * 64];
__device__ bf16  g_Wthi[458752];               // W^T packed (3 layers), hi
__device__ bf16  g_Wtlo[458752];
__device__ bf16  g_Uthi[589824];               // U^T packed (3 layers)
__device__ bf16  g_Utlo[589824];
__device__ float g_bias[1024];                 // packed b0 (for xW GEMM)
__device__ float g_biasP[1536];                // packed b1 [0:1024), b2 [1024:1536)
__device__ bf16  g_H0hi[MTOT * 256];           // h sequences (bf16 split)
__device__ bf16  g_H0lo[MTOT * 256];
__device__ bf16  g_H1hi[MTOT * 256];
__device__ bf16  g_H1lo[MTOT * 256];
__device__ bf16  g_H2hi[MTOT * 128];
__device__ bf16  g_H2lo[MTOT * 128];
__device__ unsigned int g_prog[8];             // (legacy, zeroed)
__device__ unsigned int g_bcnt[12 * 32];       // arrival counters, padded slots
__device__ unsigned int g_bgen[12 * 32];       // (legacy, zeroed)

#define WOFF0 0
#define WOFF1 (1024 * 64)
#define WOFF2 (1024 * 64 + 1024 * 256)
#define UOFF0 0
#define UOFF1 (1024 * 256)
#define UOFF2 (2 * 1024 * 256)

// ---------------------------------------------------------------------------
// sm_100-safe helpers (ldmatrix + mma.sync; no tcgen05)
// ---------------------------------------------------------------------------
__device__ __forceinline__ uint32_t smem_u32(const void* p) {
    uint32_t a;
    asm("{ .reg .u64 t; cvta.to.shared.u64 t, %1; cvt.u32.u64 %0, t; }"
        : "=r"(a) : "l"(p));
    return a;
}
__device__ __forceinline__ void ldsm_x4(uint32_t* r, uint32_t addr) {
    asm volatile("ldmatrix.sync.aligned.m8n8.x4.shared.b16 {%0,%1,%2,%3}, [%4];"
                 : "=r"(r[0]), "=r"(r[1]), "=r"(r[2]), "=r"(r[3]) : "r"(addr));
}
__device__ __forceinline__ void ldsm_x2(uint32_t* r, uint32_t addr) {
    asm volatile("ldmatrix.sync.aligned.m8n8.x2.shared.b16 {%0,%1}, [%2];"
                 : "=r"(r[0]), "=r"(r[1]) : "r"(addr));
}
__device__ __forceinline__ void mma_16816(float* d, const uint32_t* a, const uint32_t* b) {
    asm volatile(
        "mma.sync.aligned.m16n8k16.row.col.f32.bf16.bf16.f32 "
        "{%0,%1,%2,%3}, {%4,%5,%6,%7}, {%8,%9}, {%0,%1,%2,%3};\n"
        : "+f"(d[0]), "+f"(d[1]), "+f"(d[2]), "+f"(d[3])
        : "r"(a[0]), "r"(a[1]), "r"(a[2]), "r"(a[3]), "r"(b[0]), "r"(b[1]));
}
__device__ __forceinline__ float sigf(float x) {
    return __fdividef(1.f, 1.f + __expf(-x));
}
__device__ __forceinline__ float tanhf_(float x) {
    return 1.f - __fdividef(2.f, 1.f + __expf(2.f * x));
}

// ---------------------------------------------------------------------------
// Monotonic arrival-counter sync. One counter per (layer, batch-group); each
// CTA increments once per round after its h-store. Waits are bounded (raw spin
// then nanosleep fallback) so a bug degrades to wrong output, never a hang.
// ---------------------------------------------------------------------------
__device__ __forceinline__ void wait_cnt_ge(int slot, unsigned int tgt) {
    if (threadIdx.x == 0) {
        volatile unsigned int* c = &g_bcnt[slot * 32];
        bool ok = false;
        for (int it = 0; it < 4096; it++) {
            if (*c >= tgt) { ok = true; break; }
        }
        if (!ok) {
            for (int it = 0; it < (1 << 18); it++) {
                if (*c >= tgt) break;
                __nanosleep(64);
            }
        }
        __threadfence();
    }
    __syncthreads();
}

__device__ __forceinline__ void arrive_cnt(int slot) {
    __syncthreads();                    // all threads' h stores issued
    if (threadIdx.x == 0) {
        __threadfence();                // make them visible device-wide
        atomicAdd(&g_bcnt[slot * 32], 1u);
    }
}

// ---------------------------------------------------------------------------
// Consolidated conversion kernel (weights + biases + sync reset, one launch)
// ---------------------------------------------------------------------------
__device__ __forceinline__ void conv_one(const float* __restrict__ M,
                                         bf16* __restrict__ hi, bf16* __restrict__ lo,
                                         int idx, int K, int Hdim)
{
    int N = 4 * Hdim;
    int P = idx / K, k = idx - P * K;
    int n = (P & 3) * Hdim + (P >> 2);
    float v = M[(size_t)k * N + n];
    bf16 h = __float2bfloat16_rn(v);
    hi[idx] = h;
    lo[idx] = __float2bfloat16_rn(v - __bfloat162float(h));
}

__global__ void conv_all(const float* __restrict__ W0, const float* __restrict__ W1,
                         const float* __restrict__ W2, const float* __restrict__ U0,
                         const float* __restrict__ U1, const float* __restrict__ U2,
                         const float* __restrict__ b0, const float* __restrict__ b1,
                         const float* __restrict__ b2,
                         bf16* __restrict__ whi, bf16* __restrict__ wlo,
                         bf16* __restrict__ uhi, bf16* __restrict__ ulo,
                         float* __restrict__ bp0, float* __restrict__ bpP)
{
    int idx = blockIdx.x * blockDim.x + threadIdx.x;
    if (idx < 65536)        conv_one(W0, whi + WOFF0, wlo + WOFF0, idx, 64, 256);
    else if (idx < 327680)  conv_one(W1, whi + WOFF1, wlo + WOFF1, idx - 65536, 256, 256);
    else if (idx < 458752)  conv_one(W2, whi + WOFF2, wlo + WOFF2, idx - 327680, 256, 128);
    else if (idx < 720896)  conv_one(U0, uhi + UOFF0, ulo + UOFF0, idx - 458752, 256, 256);
    else if (idx < 983040)  conv_one(U1, uhi + UOFF1, ulo + UOFF1, idx - 720896, 256, 256);
    else if (idx < 1048576) conv_one(U2, uhi + UOFF2, ulo + UOFF2, idx - 983040, 128, 128);
    else {
        int i = idx - 1048576;
        if (i < 1024)       bp0[i] = b0[(i & 3) * 256 + (i >> 2)];
        else if (i < 2048)  { int P = i - 1024; bpP[P] = b1[(P & 3) * 256 + (P >> 2)]; }
        else if (i < 2560)  { int P = i - 2048; bpP[1024 + P] = b2[(P & 3) * 128 + (P >> 2)]; }
        else if (i < 2568)  g_prog[i - 2560] = 0;
        else if (i < 2952)  { int j = i - 2568; g_bcnt[j] = 0; g_bgen[j] = 0; }
    }
}

__global__ void conv_split(const float* __restrict__ in,
                           bf16* __restrict__ hi, bf16* __restrict__ lo, int n4)
{
    int i = blockIdx.x * blockDim.x + threadIdx.x;
    if (i >= n4) return;
    float4 v = ((const float4*)in)[i];
    union { bf16 b[4]; uint2 u; } H, L;
    H.b[0] = __float2bfloat16_rn(v.x);
    H.b[1] = __float2bfloat16_rn(v.y);
    H.b[2] = __float2bfloat16_rn(v.z);
    H.b[3] = __float2bfloat16_rn(v.w);
    L.b[0] = __float2bfloat16_rn(v.x - __bfloat162float(H.b[0]));
    L.b[1] = __float2bfloat16_rn(v.y - __bfloat162float(H.b[1]));
    L.b[2] = __float2bfloat16_rn(v.z - __bfloat162float(H.b[2]));
    L.b[3] = __float2bfloat16_rn(v.w - __bfloat162float(H.b[3]));
    ((uint2*)hi)[i] = H.u;
    ((uint2*)lo)[i] = L.u;
}

// ---------------------------------------------------------------------------
// mma.sync GEMM (proven): used only for layer-0 xW precompute (K=64)
// ---------------------------------------------------------------------------
#define TSTRIDE 72
#define GEMM_SMEM (4 * 128 * TSTRIDE * 2)

__global__ __launch_bounds__(256)
void mma_gemm(const bf16* __restrict__ Ahi, const bf16* __restrict__ Alo,
              const bf16* __restrict__ Bhi, const bf16* __restrict__ Blo,
              const float* __restrict__ bias, float* __restrict__ C, int K, int N)
{
    extern __shared__ bf16 sm[];
    bf16* sAhi = sm;
    bf16* sAlo = sm + 128 * TSTRIDE;
    bf16* sBhi = sm + 2 * 128 * TSTRIDE;
    bf16* sBlo = sm + 3 * 128 * TSTRIDE;
    const uint32_t uAhi = smem_u32(sAhi), uAlo = smem_u32(sAlo);
    const uint32_t uBhi = smem_u32(sBhi), uBlo = smem_u32(sBlo);

    const int tid = threadIdx.x;
    const int wid = tid >> 5, lane = tid & 31;
    const int warp_m = wid & 1, warp_n = wid >> 1;
    const int bm = blockIdx.y * 128, bn = blockIdx.x * 128;

    float acc[4][4][4];
#pragma unroll
    for (int mi = 0; mi < 4; mi++)
#pragma unroll
        for (int ni = 0; ni < 4; ni++)
#pragma unroll
            for (int f = 0; f < 4; f++) acc[mi][ni][f] = 0.f;

    const int r8  = lane & 7;
    const int grp = lane >> 3;
    const int aRowOff = ((grp & 1) ? 8 : 0) + r8;
    const int aColOff = (grp & 2) ? 8 : 0;
    const int bSel = grp & 1;

    const int nchunk = K >> 6;
    for (int c = 0; c < nchunk; c++) {
        const int k0g = c << 6;
#pragma unroll
        for (int i = 0; i < 4; i++) {
            int idx = tid + i * 256;
            int row = idx >> 3, seg = idx & 7;
            size_t ga = (size_t)(bm + row) * K + k0g + seg * 8;
            size_t gb = (size_t)(bn + row) * K + k0g + seg * 8;
            int so = row * TSTRIDE + seg * 8;
            *(uint4*)(sAhi + so) = *(const uint4*)&Ahi[ga];
            *(uint4*)(sAlo + so) = *(const uint4*)&Alo[ga];
            *(uint4*)(sBhi + so) = *(const uint4*)&Bhi[gb];
            *(uint4*)(sBlo + so) = *(const uint4*)&Blo[gb];
        }
        __syncthreads();

#pragma unroll
        for (int ks = 0; ks < 4; ks++) {
            const int k0 = ks * 16;
            uint32_t aHi[4][4], aLo[4][4], bHi[4][2], bLo[4][2];
#pragma unroll
            for (int mi = 0; mi < 4; mi++) {
                int row = warp_m * 64 + mi * 16 + aRowOff;
                uint32_t off = (uint32_t)(row * TSTRIDE + k0 + aColOff) * 2;
                ldsm_x4(aHi[mi], uAhi + off);
                ldsm_x4(aLo[mi], uAlo + off);
            }
#pragma unroll
            for (int ni = 0; ni < 4; ni++) {
                int row = warp_n * 32 + ni * 8 + r8;
                uint32_t off = (uint32_t)(row * TSTRIDE + k0 + bSel * 8) * 2;
                ldsm_x2(bHi[ni], uBhi + off);
                ldsm_x2(bLo[ni], uBlo + off);
            }
#pragma unroll
            for (int mi = 0; mi < 4; mi++)
#pragma unroll
                for (int ni = 0; ni < 4; ni++) {
                    mma_16816(acc[mi][ni], aHi[mi], bHi[ni]);
                    mma_16816(acc[mi][ni], aHi[mi], bLo[ni]);
                    mma_16816(acc[mi][ni], aLo[mi], bHi[ni]);
                }
        }
        __syncthreads();
    }

    const int tg = lane >> 2, tp = lane & 3;
#pragma unroll
    for (int mi = 0; mi < 4; mi++) {
#pragma unroll
        for (int ni = 0; ni < 4; ni++) {
            int col = bn + warp_n * 32 + ni * 8 + tp * 2;
            int row0 = bm + warp_m * 64 + mi * 16 + tg;
            float2 o0, o1;
            o0.x = acc[mi][ni][0] + bias[col];
            o0.y = acc[mi][ni][1] + bias[col + 1];
            o1.x = acc[mi][ni][2] + bias[col];
            o1.y = acc[mi][ni][3] + bias[col + 1];
            *(float2*)&C[(size_t)row0 * N + col] = o0;
            *(float2*)&C[(size_t)(row0 + 8) * N + col] = o1;
        }
    }
}

// ---------------------------------------------------------------------------
// Fused wavefront LSTM (R12 structure; counter-based sync, no group barrier).
// Per round: wait own-peer cnt>=GRPN*t -> U-stage/GEMM -> wait producer
// cnt>=PGRPN*(t+1) -> W-stage/GEMM -> gates -> store -> arrive (increment).
// ---------------------------------------------------------------------------
template<int HDIM, int KIN, int UPCv, int GRPN, int PGRPN>
__device__ void run_layer(int bb, int cb, int selfslot, int prodslot,
    const bf16* __restrict__ Uthi, const bf16* __restrict__ Utlo,
    const bf16* __restrict__ Wthi, const bf16* __restrict__ Wtlo,
    const float* __restrict__ biasp, const float* __restrict__ xW,
    const bf16* __restrict__ Hin_hi, const bf16* __restrict__ Hin_lo,
    bf16* __restrict__ Hhi, bf16* __restrict__ Hlo)
{
    constexpr int K    = HDIM;
    constexpr int PC   = 4 * UPCv;
    constexpr int WN   = PC / 4;
    constexpr int NI   = WN / 8;
    constexpr int KSU  = K / 16;
    constexpr int KS2U = K + 8;
    constexpr int U4U  = K / 8;
    constexpr int KSW  = KIN / 16;
    constexpr int KS2W = KIN + 8;
    constexpr int U4W  = KIN / 8;
    constexpr int KS2M = (KS2W > KS2U) ? KS2W : KS2U;
    constexpr int STW  = UPCv / 2;
    constexpr bool HOIST = (NI <= 2);

    extern __shared__ bf16 dyn[];
    bf16* sUhi  = dyn;                               // PC x KS2U
    bf16* sUlo  = sUhi + PC * KS2U;
    bf16* sWhi  = sUlo + PC * KS2U;                  // PC x KS2W (if KIN)
    bf16* sWlo  = sWhi + (KIN ? PC * KS2W : 0);
    bf16* sHs_hi = sWlo + (KIN ? PC * KS2W : 0);     // 64 x KS2M (A staging)
    bf16* sHs_lo = sHs_hi + 64 * KS2M;
    bf16* sSthi  = sHs_lo + 64 * KS2M;               // 64 x UPC stage-out
    bf16* sStlo  = sSthi + 64 * UPCv;
    const uint32_t uUhi = smem_u32(sUhi), uUlo = smem_u32(sUlo);
    const uint32_t uWhi = smem_u32(sWhi), uWlo = smem_u32(sWlo);
    const uint32_t uHhi = smem_u32(sHs_hi), uHlo = smem_u32(sHs_lo);

    const int tid = threadIdx.x;
    const int wid = tid >> 5, lane = tid & 31;
    const int wm = wid & 1, wn = wid >> 1;
    const int b0 = bb * 64;

    const int r8  = lane & 7;
    const int grp = lane >> 3;
    const int aRowOff = ((grp & 1) ? 8 : 0) + r8;
    const int aColOff = (grp & 2) ? 8 : 0;
    const int bSel = grp & 1;
    const int tg = lane >> 2, tp = lane & 3;
    const bool evenp = (tp & 1) == 0;

    // Persistent U^T slice (packed rows cb*PC ..)
    for (int idx = tid; idx < PC * U4U; idx += 256) {
        int p = idx / U4U, q = idx - p * U4U;
        size_t g = (size_t)(cb * PC + p) * K + q * 8;
        *(uint4*)(sUhi + p * KS2U + q * 8) = *(const uint4*)&Uthi[g];
        *(uint4*)(sUlo + p * KS2U + q * 8) = *(const uint4*)&Utlo[g];
    }
    if constexpr (KIN > 0) {
        for (int idx = tid; idx < PC * U4W; idx += 256) {
            int p = idx / U4W, q = idx - p * U4W;
            size_t g = (size_t)(cb * PC + p) * KIN + q * 8;
            *(uint4*)(sWhi + p * KS2W + q * 8) = *(const uint4*)&Wthi[g];
            *(uint4*)(sWlo + p * KS2W + q * 8) = *(const uint4*)&Wtlo[g];
        }
    }
    __syncthreads();

    // Hoist step-invariant U-hi fragments into registers (small NI only)
    uint32_t uHiReg[HOIST ? KSU : 1][HOIST ? NI : 1][2];
    if constexpr (HOIST) {
#pragma unroll
        for (int ks = 0; ks < KSU; ks++)
#pragma unroll
            for (int ni = 0; ni < NI; ni++) {
                uint32_t off = (uint32_t)((wn * WN + ni * 8 + r8) * KS2U
                                          + ks * 16 + bSel * 8) * 2;
                ldsm_x2(uHiReg[ks][ni], uUhi + off);
            }
    }

    int colg[NI], uLoc[NI];
#pragma unroll
    for (int ni = 0; ni < NI; ni++) {
        int pcl = wn * WN + ni * 8 + 2 * tp;
        colg[ni] = cb * PC + pcl;
        uLoc[ni] = pcl >> 2;
    }
    float bs[NI][2];
    if constexpr (KIN > 0) {
#pragma unroll
        for (int ni = 0; ni < NI; ni++) {
            bs[ni][0] = biasp[colg[ni]];
            bs[ni][1] = biasp[colg[ni] + 1];
        }
    }

    float cst[2][NI][2];
#pragma unroll
    for (int mi = 0; mi < 2; mi++)
#pragma unroll
        for (int ni = 0; ni < NI; ni++) { cst[mi][ni][0] = 0.f; cst[mi][ni][1] = 0.f; }

    float nxt[2][NI][4];
    if constexpr (KIN == 0) {
#pragma unroll
        for (int mi = 0; mi < 2; mi++) {
            size_t row = (size_t)(b0 + wm * 32 + mi * 16 + tg);
#pragma unroll
            for (int ni = 0; ni < NI; ni++) {
                float2 a = *(const float2*)&xW[(row * TLEN) * (4 * HDIM) + colg[ni]];
                float2 b = *(const float2*)&xW[((row + 8) * TLEN) * (4 * HDIM) + colg[ni]];
                nxt[mi][ni][0] = a.x; nxt[mi][ni][1] = a.y;
                nxt[mi][ni][2] = b.x; nxt[mi][ni][3] = b.y;
            }
        }
    }

    for (int t = 0; t < TLEN; t++) {
        float acc[2][NI][4];
#pragma unroll
        for (int mi = 0; mi < 2; mi++)
#pragma unroll
            for (int ni = 0; ni < NI; ni++) {
                if constexpr (KIN == 0) {
                    acc[mi][ni][0] = nxt[mi][ni][0]; acc[mi][ni][1] = nxt[mi][ni][1];
                    acc[mi][ni][2] = nxt[mi][ni][2]; acc[mi][ni][3] = nxt[mi][ni][3];
                } else {
                    acc[mi][ni][0] = bs[ni][0]; acc[mi][ni][1] = bs[ni][1];
                    acc[mi][ni][2] = bs[ni][0]; acc[mi][ni][3] = bs[ni][1];
                }
            }

        // ---- Recurrent GEMM FIRST (own h(t-1); peers gated by counter) ----
        if (t > 0) {
            wait_cnt_ge(selfslot, (unsigned)(GRPN * t));
            for (int idx = tid; idx < 64 * U4U; idx += 256) {
                int r = idx / U4U, q = idx - r * U4U;
                size_t g = ((size_t)(b0 + r) * TLEN + (t - 1)) * HDIM + q * 8;
                *(uint4*)(sHs_hi + r * KS2U + q * 8) = *(const uint4*)&Hhi[g];
                *(uint4*)(sHs_lo + r * KS2U + q * 8) = *(const uint4*)&Hlo[g];
            }
            __syncthreads();
#pragma unroll
            for (int ks = 0; ks < KSU; ks++) {
                uint32_t ahi[2][4], alo[2][4];
#pragma unroll
                for (int mi = 0; mi < 2; mi++) {
                    uint32_t aoff = (uint32_t)((wm * 32 + mi * 16 + aRowOff) * KS2U
                                               + ks * 16 + aColOff) * 2;
                    ldsm_x4(ahi[mi], uHhi + aoff);
                    ldsm_x4(alo[mi], uHlo + aoff);
                }
#pragma unroll
                for (int ni = 0; ni < NI; ni++) {
                    uint32_t bh[2], bl[2];
                    uint32_t boff = (uint32_t)((wn * WN + ni * 8 + r8) * KS2U
                                               + ks * 16 + bSel * 8) * 2;
                    if constexpr (HOIST) {
                        bh[0] = uHiReg[ks][ni][0]; bh[1] = uHiReg[ks][ni][1];
                    } else {
                        ldsm_x2(bh, uUhi + boff);
                    }
                    ldsm_x2(bl, uUlo + boff);
#pragma unroll
                    for (int mi = 0; mi < 2; mi++) {
                        mma_16816(acc[mi][ni], ahi[mi], bh);
                        mma_16816(acc[mi][ni], ahi[mi], bl);
                        mma_16816(acc[mi][ni], alo[mi], bh);
                    }
                }
            }
            __syncthreads();   // sHs reads done before W-phase restages
        }

        // ---- Producer wait + input GEMM (skew hidden under U-phase) ----
        if constexpr (KIN > 0) {
            wait_cnt_ge(prodslot, (unsigned)(PGRPN * (t + 1)));
            for (int idx = tid; idx < 64 * U4W; idx += 256) {
                int r = idx / U4W, q = idx - r * U4W;
                size_t g = ((size_t)(b0 + r) * TLEN + t) * KIN + q * 8;
                *(uint4*)(sHs_hi + r * KS2W + q * 8) = *(const uint4*)&Hin_hi[g];
                *(uint4*)(sHs_lo + r * KS2W + q * 8) = *(const uint4*)&Hin_lo[g];
            }
            __syncthreads();
#pragma unroll
            for (int ks = 0; ks < KSW; ks++) {
                uint32_t ahi[2][4], alo[2][4];
#pragma unroll
                for (int mi = 0; mi < 2; mi++) {
                    uint32_t aoff = (uint32_t)((wm * 32 + mi * 16 + aRowOff) * KS2W
                                               + ks * 16 + aColOff) * 2;
                    ldsm_x4(ahi[mi], uHhi + aoff);
                    ldsm_x4(alo[mi], uHlo + aoff);
                }
#pragma unroll
                for (int ni = 0; ni < NI; ni++) {
                    uint32_t bh[2], bl[2];
                    uint32_t boff = (uint32_t)((wn * WN + ni * 8 + r8) * KS2W
                                               + ks * 16 + bSel * 8) * 2;
                    ldsm_x2(bh, uWhi + boff);
                    ldsm_x2(bl, uWlo + boff);
#pragma unroll
                    for (int mi = 0; mi < 2; mi++) {
                        mma_16816(acc[mi][ni], ahi[mi], bh);
                        mma_16816(acc[mi][ni], ahi[mi], bl);
                        mma_16816(acc[mi][ni], alo[mi], bh);
                    }
                }
            }
        }

        // Gates (even tp: i,f | odd tp: g,o of same unit); stage h out
#pragma unroll
        for (int mi = 0; mi < 2; mi++) {
#pragma unroll
            for (int ni = 0; ni < NI; ni++) {
                float v0, v1, v2, v3;
                if (evenp) {
                    v0 = sigf(acc[mi][ni][0]); v1 = sigf(acc[mi][ni][1]);
                    v2 = sigf(acc[mi][ni][2]); v3 = sigf(acc[mi][ni][3]);
                } else {
                    v0 = tanhf_(acc[mi][ni][0]); v1 = sigf(acc[mi][ni][1]);
                    v2 = tanhf_(acc[mi][ni][2]); v3 = sigf(acc[mi][ni][3]);
                }
                float p0 = __shfl_xor_sync(0xffffffffu, v0, 1);
                float p1 = __shfl_xor_sync(0xffffffffu, v1, 1);
                float p2 = __shfl_xor_sync(0xffffffffu, v2, 1);
                float p3 = __shfl_xor_sync(0xffffffffu, v3, 1);
                float i0 = evenp ? v0 : p0, f0 = evenp ? v1 : p1;
                float g0 = evenp ? p0 : v0, o0 = evenp ? p1 : v1;
                float i1 = evenp ? v2 : p2, f1 = evenp ? v3 : p3;
                float g1 = evenp ? p2 : v2, o1 = evenp ? p3 : v3;

                float c0 = fmaf(f0, cst[mi][ni][0], i0 * g0);
                float c1 = fmaf(f1, cst[mi][ni][1], i1 * g1);
                cst[mi][ni][0] = c0;
                cst[mi][ni][1] = c1;
                float h0 = o0 * tanhf_(c0);
                float h1 = o1 * tanhf_(c1);

                if (evenp) {
                    int r0 = wm * 32 + mi * 16 + tg, r1 = r0 + 8;
                    bf16 h0h = __float2bfloat16_rn(h0);
                    bf16 h1h = __float2bfloat16_rn(h1);
                    sSthi[r0 * UPCv + uLoc[ni]] = h0h;
                    sStlo[r0 * UPCv + uLoc[ni]] = __float2bfloat16_rn(h0 - __bfloat162float(h0h));
                    sSthi[r1 * UPCv + uLoc[ni]] = h1h;
                    sStlo[r1 * UPCv + uLoc[ni]] = __float2bfloat16_rn(h1 - __bfloat162float(h1h));
                }
            }
        }

        // L0: prefetch next xW (hidden under store)
        if constexpr (KIN == 0) {
            if (t + 1 < TLEN) {
#pragma unroll
                for (int mi = 0; mi < 2; mi++) {
                    size_t row = (size_t)(b0 + wm * 32 + mi * 16 + tg);
#pragma unroll
                    for (int ni = 0; ni < NI; ni++) {
                        float2 a = *(const float2*)&xW[(row * TLEN + t + 1) * (4 * HDIM) + colg[ni]];
                        float2 b = *(const float2*)&xW[((row + 8) * TLEN + t + 1) * (4 * HDIM) + colg[ni]];
                        nxt[mi][ni][0] = a.x; nxt[mi][ni][1] = a.y;
                        nxt[mi][ni][2] = b.x; nxt[mi][ni][3] = b.y;
                    }
                }
            }
        }

        __syncthreads();
        // Coalesced h store (hi & lo)
        for (int idx = tid; idx < 64 * STW; idx += 256) {
            int r = idx / STW, q = idx - r * STW;
            size_t g = ((size_t)(b0 + r) * TLEN + t) * HDIM + cb * UPCv + q * 2;
            *(uint32_t*)&Hhi[g] = ((const uint32_t*)sSthi)[r * STW + q];
            *(uint32_t*)&Hlo[g] = ((const uint32_t*)sStlo)[r * STW + q];
        }

        arrive_cnt(selfslot);   // publish this round (non-blocking)
    }
}

__global__ __launch_bounds__(256, 1) void fused_lstm()
{
    int bx = blockIdx.x;
    if (bx < 32) {
        int bb = bx >> 3, cb = bx & 7;
        run_layer<256, 0, 32, 8, 1>(bb, cb, bb, -1,
            g_Uthi + UOFF0, g_Utlo + UOFF0, nullptr, nullptr,
            nullptr, g_xW, nullptr, nullptr, g_H0hi, g_H0lo);
    } else if (bx < 96) {
        int l = bx - 32;
        int bb = l >> 4, cb = l & 15;
        run_layer<256, 256, 16, 16, 8>(bb, cb, 4 + bb, bb,
            g_Uthi + UOFF1, g_Utlo + UOFF1, g_Wthi + WOFF1, g_Wtlo + WOFF1,
            g_biasP, nullptr, g_H0hi, g_H0lo, g_H1hi, g_H1lo);
    } else {
        int l = bx - 96;
        int bb = l >> 3, cb = l & 7;
        run_layer<128, 256, 16, 8, 16>(bb, cb, 8 + bb, 4 + bb,
            g_Uthi + UOFF2, g_Utlo + UOFF2, g_Wthi + WOFF2, g_Wtlo + WOFF2,
            g_biasP + 1024, nullptr, g_H1hi, g_H1lo, g_H2hi, g_H2lo);
    }
}

// ---------------------------------------------------------------------------
// Final dense: out[b,d] = (hi+lo)[b,T-1,:128] @ Wd + bd
// ---------------------------------------------------------------------------
__global__ void dense_kernel(const float* __restrict__ Wd, const float* __restrict__ bd,
                             float* __restrict__ out)
{
    int b = blockIdx.x;
    int d = threadIdx.x;
    size_t base = ((size_t)b * TLEN + (TLEN - 1)) * 128;
    float acc = 0.f;
#pragma unroll 4
    for (int k = 0; k < 128; k++) {
        float h = __bfloat162float(g_H2hi[base + k]) + __bfloat162float(g_H2lo[base + k]);
        acc = fmaf(h, Wd[k * 64 + d], acc);
    }
    out[b * 64 + d] = acc + bd[d];
}

// ---------------------------------------------------------------------------
// Launch sequence: [0] conv_all  [1] conv_split  [2] mma_gemm
//                  [3] fused_lstm (ncu target)  [4] dense
// ---------------------------------------------------------------------------
#define FUSED_SMEM ((128 * 264 * 2 + 64 * 264 * 2 + 64 * 32 * 2) * 2)

extern "C" void kernel_launch(void* const* d_in, const int* in_sizes, int n_in,
                              void* d_out, int out_size)
{
    (void)in_sizes; (void)n_in; (void)out_size;
    const float* x  = (const float*)d_in[0];
    const float* W0 = (const float*)d_in[1];
    const float* U0 = (const float*)d_in[2];
    const float* b0 = (const float*)d_in[3];
    const float* W1 = (const float*)d_in[4];
    const float* U1 = (const float*)d_in[5];
    const float* b1 = (const float*)d_in[6];
    const float* W2 = (const float*)d_in[7];
    const float* U2 = (const float*)d_in[8];
    const float* b2 = (const float*)d_in[9];
    const float* Wd = (const float*)d_in[10];
    const float* bd = (const float*)d_in[11];
    float* out = (float*)d_out;

    void* p;
    cudaGetSymbolAddress(&p, g_xW);    float* xw = (float*)p;
    cudaGetSymbolAddress(&p, g_Ahi);   bf16* ahi = (bf16*)p;
    cudaGetSymbolAddress(&p, g_Alo);   bf16* alo = (bf16*)p;
    cudaGetSymbolAddress(&p, g_Wthi);  bf16* whi = (bf16*)p;
    cudaGetSymbolAddress(&p, g_Wtlo);  bf16* wlo = (bf16*)p;
    cudaGetSymbolAddress(&p, g_Uthi);  bf16* uhi = (bf16*)p;
    cudaGetSymbolAddress(&p, g_Utlo);  bf16* ulo = (bf16*)p;
    cudaGetSymbolAddress(&p, g_bias);  float* bp0 = (float*)p;
    cudaGetSymbolAddress(&p, g_biasP); float* bpP = (float*)p;

    cudaFuncSetAttribute(mma_gemm, cudaFuncAttributeMaxDynamicSharedMemorySize, GEMM_SMEM);
    cudaFuncSetAttribute(fused_lstm, cudaFuncAttributeMaxDynamicSharedMemorySize, FUSED_SMEM);

    // [0] all weight/bias conversion + counter reset (one launch)
    conv_all<<<4108, 256>>>(W0, W1, W2, U0, U1, U2, b0, b1, b2,
                            whi, wlo, uhi, ulo, bp0, bpP);
    // [1] x split
    conv_split<<<(MTOT * 64 / 4 + 255) / 256, 256>>>(x, ahi, alo, MTOT * 64 / 4);
    // [2] layer-0 xW precompute
    mma_gemm<<<dim3(8, MTOT / 128), 256, GEMM_SMEM>>>(ahi, alo, whi + WOFF0, wlo + WOFF0,
                                                      bp0, xw, 64, 1024);
    // [3] fused wavefront (profiling target)
    fused_lstm<<<128, 256, FUSED_SMEM>>>();
    // [4] dense head
    dense_kernel<<<BSZ, 64>>>(Wd, bd, out);
}

// round 16
// speedup vs baseline: 1.2955x; 1.0330x over previous
#include <cuda_runtime.h>
#include <cuda_bf16.h>
#include <cstdint>
#include <cstddef>

#define BSZ  256
#define TLEN 512
#define DIN  64
#define MTOT (BSZ * TLEN)

typedef __nv_bfloat16 bf16;

template<int V> struct IC { static constexpr int value = V; };

// ---------------------------------------------------------------------------
// Device-global scratch
// ---------------------------------------------------------------------------
__device__ float g_xW[MTOT * 1024];            // xW0 = x@W0 + b0, packed cols
__device__ bf16  g_Ahi[MTOT * 64];             // x split (layer-0 GEMM A)
__device__ bf16  g_Alo[MTOT * 64];
__device__ bf16  g_Wthi[458752];               // W^T packed (3 layers), hi
__device__ bf16  g_Wtlo[458752];
__device__ bf16  g_Uthi[589824];               // U^T packed (3 layers)
__device__ bf16  g_Utlo[589824];
__device__ float g_bias[1024];                 // packed b0 (for xW GEMM)
__device__ float g_biasP[1536];                // packed b1 [0:1024), b2 [1024:1536)
__device__ bf16  g_H0hi[MTOT * 256];           // h sequences (bf16 split)
__device__ bf16  g_H0lo[MTOT * 256];
__device__ bf16  g_H1hi[MTOT * 256];
__device__ bf16  g_H1lo[MTOT * 256];
__device__ bf16  g_H2hi[MTOT * 128];
__device__ bf16  g_H2lo[MTOT * 128];
__device__ unsigned int g_prog[8];             // (legacy, zeroed)
__device__ unsigned int g_bcnt[12 * 32];       // arrival counters, padded slots
__device__ unsigned int g_bgen[12 * 32];       // (legacy, zeroed)

#define WOFF0 0
#define WOFF1 (1024 * 64)
#define WOFF2 (1024 * 64 + 1024 * 256)
#define UOFF0 0
#define UOFF1 (1024 * 256)
#define UOFF2 (2 * 1024 * 256)

// ---------------------------------------------------------------------------
// sm_100-safe helpers (ldmatrix + mma.sync + cp.async; no tcgen05)
// ---------------------------------------------------------------------------
__device__ __forceinline__ uint32_t smem_u32(const void* p) {
    uint32_t a;
    asm("{ .reg .u64 t; cvta.to.shared.u64 t, %1; cvt.u32.u64 %0, t; }"
        : "=r"(a) : "l"(p));
    return a;
}
__device__ __forceinline__ void ldsm_x4(uint32_t* r, uint32_t addr) {
    asm volatile("ldmatrix.sync.aligned.m8n8.x4.shared.b16 {%0,%1,%2,%3}, [%4];"
                 : "=r"(r[0]), "=r"(r[1]), "=r"(r[2]), "=r"(r[3]) : "r"(addr));
}
__device__ __forceinline__ void ldsm_x2(uint32_t* r, uint32_t addr) {
    asm volatile("ldmatrix.sync.aligned.m8n8.x2.shared.b16 {%0,%1}, [%2];"
                 : "=r"(r[0]), "=r"(r[1]) : "r"(addr));
}
__device__ __forceinline__ void mma_16816(float* d, const uint32_t* a, const uint32_t* b) {
    asm volatile(
        "mma.sync.aligned.m16n8k16.row.col.f32.bf16.bf16.f32 "
        "{%0,%1,%2,%3}, {%4,%5,%6,%7}, {%8,%9}, {%0,%1,%2,%3};\n"
        : "+f"(d[0]), "+f"(d[1]), "+f"(d[2]), "+f"(d[3])
        : "r"(a[0]), "r"(a[1]), "r"(a[2]), "r"(a[3]), "r"(b[0]), "r"(b[1]));
}
__device__ __forceinline__ float sigf(float x) {
    return __fdividef(1.f, 1.f + __expf(-x));
}
__device__ __forceinline__ float tanhf_(float x) {
    return 1.f - __fdividef(2.f, 1.f + __expf(2.f * x));
}

__device__ __forceinline__ void cp16(uint32_t s, const void* g) {
    asm volatile("cp.async.cg.shared.global [%0], [%1], 16;" :: "r"(s), "l"(g) : "memory");
}
#define CP_COMMIT() asm volatile("cp.async.commit_group;" ::: "memory")
#define CP_WAIT1()  asm volatile("cp.async.wait_group 1;" ::: "memory")
#define CP_WAIT0()  asm volatile("cp.async.wait_group 0;" ::: "memory")

// Stage one K-half (cols [half*K/2, ..)) of a 64-row hi/lo pair via cp.async.
template<int U4R, int KS2>
__device__ __forceinline__ void stage_half_async(int tid, int half,
    const bf16* __restrict__ Ghi, const bf16* __restrict__ Glo,
    size_t gbase, size_t rowstride, uint32_t uHhi, uint32_t uHlo)
{
    for (int idx = tid; idx < 64 * U4R; idx += 256) {
        int r = idx / U4R, q = (idx - r * U4R) + half * U4R;
        size_t g = gbase + (size_t)r * rowstride + (size_t)q * 8;
        uint32_t s = (uint32_t)(r * KS2 + q * 8) * 2;
        cp16(uHhi + s, Ghi + g);
        cp16(uHlo + s, Glo + g);
    }
}

// ---------------------------------------------------------------------------
// Monotonic arrival-counter sync (bounded; bug -> wrong output, never a hang)
// ---------------------------------------------------------------------------
__device__ __forceinline__ void wait_cnt_ge(int slot, unsigned int tgt) {
    if (threadIdx.x == 0) {
        volatile unsigned int* c = &g_bcnt[slot * 32];
        bool ok = false;
        for (int it = 0; it < 4096; it++) {
            if (*c >= tgt) { ok = true; break; }
        }
        if (!ok) {
            for (int it = 0; it < (1 << 18); it++) {
                if (*c >= tgt) break;
                __nanosleep(64);
            }
        }
        __threadfence();
    }
    __syncthreads();
}

__device__ __forceinline__ void arrive_cnt(int slot) {
    __syncthreads();
    if (threadIdx.x == 0) {
        __threadfence();
        atomicAdd(&g_bcnt[slot * 32], 1u);
    }
}

// ---------------------------------------------------------------------------
// Consolidated conversion kernel (weights + biases + sync reset, one launch)
// ---------------------------------------------------------------------------
__device__ __forceinline__ void conv_one(const float* __restrict__ M,
                                         bf16* __restrict__ hi, bf16* __restrict__ lo,
                                         int idx, int K, int Hdim)
{
    int N = 4 * Hdim;
    int P = idx / K, k = idx - P * K;
    int n = (P & 3) * Hdim + (P >> 2);
    float v = M[(size_t)k * N + n];
    bf16 h = __float2bfloat16_rn(v);
    hi[idx] = h;
    lo[idx] = __float2bfloat16_rn(v - __bfloat162float(h));
}

__global__ void conv_all(const float* __restrict__ W0, const float* __restrict__ W1,
                         const float* __restrict__ W2, const float* __restrict__ U0,
                         const float* __restrict__ U1, const float* __restrict__ U2,
                         const float* __restrict__ b0, const float* __restrict__ b1,
                         const float* __restrict__ b2,
                         bf16* __restrict__ whi, bf16* __restrict__ wlo,
                         bf16* __restrict__ uhi, bf16* __restrict__ ulo,
                         float* __restrict__ bp0, float* __restrict__ bpP)
{
    int idx = blockIdx.x * blockDim.x + threadIdx.x;
    if (idx < 65536)        conv_one(W0, whi + WOFF0, wlo + WOFF0, idx, 64, 256);
    else if (idx < 327680)  conv_one(W1, whi + WOFF1, wlo + WOFF1, idx - 65536, 256, 256);
    else if (idx < 458752)  conv_one(W2, whi + WOFF2, wlo + WOFF2, idx - 327680, 256, 128);
    else if (idx < 720896)  conv_one(U0, uhi + UOFF0, ulo + UOFF0, idx - 458752, 256, 256);
    else if (idx < 983040)  conv_one(U1, uhi + UOFF1, ulo + UOFF1, idx - 720896, 256, 256);
    else if (idx < 1048576) conv_one(U2, uhi + UOFF2, ulo + UOFF2, idx - 983040, 128, 128);
    else {
        int i = idx - 1048576;
        if (i < 1024)       bp0[i] = b0[(i & 3) * 256 + (i >> 2)];
        else if (i < 2048)  { int P = i - 1024; bpP[P] = b1[(P & 3) * 256 + (P >> 2)]; }
        else if (i < 2560)  { int P = i - 2048; bpP[1024 + P] = b2[(P & 3) * 128 + (P >> 2)]; }
        else if (i < 2568)  g_prog[i - 2560] = 0;
        else if (i < 2952)  { int j = i - 2568; g_bcnt[j] = 0; g_bgen[j] = 0; }
    }
}

__global__ void conv_split(const float* __restrict__ in,
                           bf16* __restrict__ hi, bf16* __restrict__ lo, int n4)
{
    int i = blockIdx.x * blockDim.x + threadIdx.x;
    if (i >= n4) return;
    float4 v = ((const float4*)in)[i];
    union { bf16 b[4]; uint2 u; } H, L;
    H.b[0] = __float2bfloat16_rn(v.x);
    H.b[1] = __float2bfloat16_rn(v.y);
    H.b[2] = __float2bfloat16_rn(v.z);
    H.b[3] = __float2bfloat16_rn(v.w);
    L.b[0] = __float2bfloat16_rn(v.x - __bfloat162float(H.b[0]));
    L.b[1] = __float2bfloat16_rn(v.y - __bfloat162float(H.b[1]));
    L.b[2] = __float2bfloat16_rn(v.z - __bfloat162float(H.b[2]));
    L.b[3] = __float2bfloat16_rn(v.w - __bfloat162float(H.b[3]));
    ((uint2*)hi)[i] = H.u;
    ((uint2*)lo)[i] = L.u;
}

// ---------------------------------------------------------------------------
// mma.sync GEMM (proven): used only for layer-0 xW precompute (K=64)
// ---------------------------------------------------------------------------
#define TSTRIDE 72
#define GEMM_SMEM (4 * 128 * TSTRIDE * 2)

__global__ __launch_bounds__(256)
void mma_gemm(const bf16* __restrict__ Ahi, const bf16* __restrict__ Alo,
              const bf16* __restrict__ Bhi, const bf16* __restrict__ Blo,
              const float* __restrict__ bias, float* __restrict__ C, int K, int N)
{
    extern __shared__ bf16 sm[];
    bf16* sAhi = sm;
    bf16* sAlo = sm + 128 * TSTRIDE;
    bf16* sBhi = sm + 2 * 128 * TSTRIDE;
    bf16* sBlo = sm + 3 * 128 * TSTRIDE;
    const uint32_t uAhi = smem_u32(sAhi), uAlo = smem_u32(sAlo);
    const uint32_t uBhi = smem_u32(sBhi), uBlo = smem_u32(sBlo);

    const int tid = threadIdx.x;
    const int wid = tid >> 5, lane = tid & 31;
    const int warp_m = wid & 1, warp_n = wid >> 1;
    const int bm = blockIdx.y * 128, bn = blockIdx.x * 128;

    float acc[4][4][4];
#pragma unroll
    for (int mi = 0; mi < 4; mi++)
#pragma unroll
        for (int ni = 0; ni < 4; ni++)
#pragma unroll
            for (int f = 0; f < 4; f++) acc[mi][ni][f] = 0.f;

    const int r8  = lane & 7;
    const int grp = lane >> 3;
    const int aRowOff = ((grp & 1) ? 8 : 0) + r8;
    const int aColOff = (grp & 2) ? 8 : 0;
    const int bSel = grp & 1;

    const int nchunk = K >> 6;
    for (int c = 0; c < nchunk; c++) {
        const int k0g = c << 6;
#pragma unroll
        for (int i = 0; i < 4; i++) {
            int idx = tid + i * 256;
            int row = idx >> 3, seg = idx & 7;
            size_t ga = (size_t)(bm + row) * K + k0g + seg * 8;
            size_t gb = (size_t)(bn + row) * K + k0g + seg * 8;
            int so = row * TSTRIDE + seg * 8;
            *(uint4*)(sAhi + so) = *(const uint4*)&Ahi[ga];
            *(uint4*)(sAlo + so) = *(const uint4*)&Alo[ga];
            *(uint4*)(sBhi + so) = *(const uint4*)&Bhi[gb];
            *(uint4*)(sBlo + so) = *(const uint4*)&Blo[gb];
        }
        __syncthreads();

#pragma unroll
        for (int ks = 0; ks < 4; ks++) {
            const int k0 = ks * 16;
            uint32_t aHi[4][4], aLo[4][4], bHi[4][2], bLo[4][2];
#pragma unroll
            for (int mi = 0; mi < 4; mi++) {
                int row = warp_m * 64 + mi * 16 + aRowOff;
                uint32_t off = (uint32_t)(row * TSTRIDE + k0 + aColOff) * 2;
                ldsm_x4(aHi[mi], uAhi + off);
                ldsm_x4(aLo[mi], uAlo + off);
            }
#pragma unroll
            for (int ni = 0; ni < 4; ni++) {
                int row = warp_n * 32 + ni * 8 + r8;
                uint32_t off = (uint32_t)(row * TSTRIDE + k0 + bSel * 8) * 2;
                ldsm_x2(bHi[ni], uBhi + off);
                ldsm_x2(bLo[ni], uBlo + off);
            }
#pragma unroll
            for (int mi = 0; mi < 4; mi++)
#pragma unroll
                for (int ni = 0; ni < 4; ni++) {
                    mma_16816(acc[mi][ni], aHi[mi], bHi[ni]);
                    mma_16816(acc[mi][ni], aHi[mi], bLo[ni]);
                    mma_16816(acc[mi][ni], aLo[mi], bHi[ni]);
                }
        }
        __syncthreads();
    }

    const int tg = lane >> 2, tp = lane & 3;
#pragma unroll
    for (int mi = 0; mi < 4; mi++) {
#pragma unroll
        for (int ni = 0; ni < 4; ni++) {
            int col = bn + warp_n * 32 + ni * 8 + tp * 2;
            int row0 = bm + warp_m * 64 + mi * 16 + tg;
            float2 o0, o1;
            o0.x = acc[mi][ni][0] + bias[col];
            o0.y = acc[mi][ni][1] + bias[col + 1];
            o1.x = acc[mi][ni][2] + bias[col];
            o1.y = acc[mi][ni][3] + bias[col + 1];
            *(float2*)&C[(size_t)row0 * N + col] = o0;
            *(float2*)&C[(size_t)(row0 + 8) * N + col] = o1;
        }
    }
}

// ---------------------------------------------------------------------------
// Fused wavefront LSTM: counter sync + cp.async double-buffered staging.
// K-halves pipelined; on L1 (K==KIN) W-phase staging overlaps U-phase GEMM.
// ---------------------------------------------------------------------------
template<int HDIM, int KIN, int UPCv, int GRPN, int PGRPN>
__device__ void run_layer(int bb, int cb, int selfslot, int prodslot,
    const bf16* __restrict__ Uthi, const bf16* __restrict__ Utlo,
    const bf16* __restrict__ Wthi, const bf16* __restrict__ Wtlo,
    const float* __restrict__ biasp, const float* __restrict__ xW,
    const bf16* __restrict__ Hin_hi, const bf16* __restrict__ Hin_lo,
    bf16* __restrict__ Hhi, bf16* __restrict__ Hlo)
{
    constexpr int K    = HDIM;
    constexpr int PC   = 4 * UPCv;
    constexpr int WN   = PC / 4;
    constexpr int NI   = WN / 8;
    constexpr int KSU  = K / 16;
    constexpr int KSUh = KSU / 2;
    constexpr int KS2U = K + 8;
    constexpr int U4U  = K / 8;
    constexpr int U4Uh = U4U / 2;
    constexpr int KSW  = KIN / 16;
    constexpr int KSWh = (KIN > 0) ? KSW / 2 : 0;
    constexpr int KS2W = KIN + 8;
    constexpr int U4W  = KIN / 8;
    constexpr int U4Wh = (KIN > 0) ? U4W / 2 : 0;
    constexpr int KS2M = (KS2W > KS2U) ? KS2W : KS2U;
    constexpr int STW  = UPCv / 2;
    constexpr bool HOIST = (NI <= 2);
    constexpr bool OVERLAP = (KIN == HDIM);   // same smem stride -> safe overlap

    extern __shared__ bf16 dyn[];
    bf16* sUhi  = dyn;                               // PC x KS2U
    bf16* sUlo  = sUhi + PC * KS2U;
    bf16* sWhi  = sUlo + PC * KS2U;                  // PC x KS2W (if KIN)
    bf16* sWlo  = sWhi + (KIN ? PC * KS2W : 0);
    bf16* sHs_hi = sWlo + (KIN ? PC * KS2W : 0);     // 64 x KS2M (A staging)
    bf16* sHs_lo = sHs_hi + 64 * KS2M;
    bf16* sSthi  = sHs_lo + 64 * KS2M;               // 64 x UPC stage-out
    bf16* sStlo  = sSthi + 64 * UPCv;
    const uint32_t uUhi = smem_u32(sUhi), uUlo = smem_u32(sUlo);
    const uint32_t uWhi = smem_u32(sWhi), uWlo = smem_u32(sWlo);
    const uint32_t uHhi = smem_u32(sHs_hi), uHlo = smem_u32(sHs_lo);

    const int tid = threadIdx.x;
    const int wid = tid >> 5, lane = tid & 31;
    const int wm = wid & 1, wn = wid >> 1;
    const int b0 = bb * 64;

    const int r8  = lane & 7;
    const int grp = lane >> 3;
    const int aRowOff = ((grp & 1) ? 8 : 0) + r8;
    const int aColOff = (grp & 2) ? 8 : 0;
    const int bSel = grp & 1;
    const int tg = lane >> 2, tp = lane & 3;
    const bool evenp = (tp & 1) == 0;

    // Persistent U^T slice (packed rows cb*PC ..)
    for (int idx = tid; idx < PC * U4U; idx += 256) {
        int p = idx / U4U, q = idx - p * U4U;
        size_t g = (size_t)(cb * PC + p) * K + q * 8;
        *(uint4*)(sUhi + p * KS2U + q * 8) = *(const uint4*)&Uthi[g];
        *(uint4*)(sUlo + p * KS2U + q * 8) = *(const uint4*)&Utlo[g];
    }
    if constexpr (KIN > 0) {
        for (int idx = tid; idx < PC * U4W; idx += 256) {
            int p = idx / U4W, q = idx - p * U4W;
            size_t g = (size_t)(cb * PC + p) * KIN + q * 8;
            *(uint4*)(sWhi + p * KS2W + q * 8) = *(const uint4*)&Wthi[g];
            *(uint4*)(sWlo + p * KS2W + q * 8) = *(const uint4*)&Wtlo[g];
        }
    }
    __syncthreads();

    // Hoist step-invariant U-hi fragments into registers (small NI only)
    uint32_t uHiReg[HOIST ? KSU : 1][HOIST ? NI : 1][2];
    if constexpr (HOIST) {
#pragma unroll
        for (int ks = 0; ks < KSU; ks++)
#pragma unroll
            for (int ni = 0; ni < NI; ni++) {
                uint32_t off = (uint32_t)((wn * WN + ni * 8 + r8) * KS2U
                                          + ks * 16 + bSel * 8) * 2;
                ldsm_x2(uHiReg[ks][ni], uUhi + off);
            }
    }

    int colg[NI], uLoc[NI];
#pragma unroll
    for (int ni = 0; ni < NI; ni++) {
        int pcl = wn * WN + ni * 8 + 2 * tp;
        colg[ni] = cb * PC + pcl;
        uLoc[ni] = pcl >> 2;
    }
    float bs[NI][2];
    if constexpr (KIN > 0) {
#pragma unroll
        for (int ni = 0; ni < NI; ni++) {
            bs[ni][0] = biasp[colg[ni]];
            bs[ni][1] = biasp[colg[ni] + 1];
        }
    }

    float cst[2][NI][2];
#pragma unroll
    for (int mi = 0; mi < 2; mi++)
#pragma unroll
        for (int ni = 0; ni < NI; ni++) { cst[mi][ni][0] = 0.f; cst[mi][ni][1] = 0.f; }

    float nxt[2][NI][4];
    if constexpr (KIN == 0) {
#pragma unroll
        for (int mi = 0; mi < 2; mi++) {
            size_t row = (size_t)(b0 + wm * 32 + mi * 16 + tg);
#pragma unroll
            for (int ni = 0; ni < NI; ni++) {
                float2 a = *(const float2*)&xW[(row * TLEN) * (4 * HDIM) + colg[ni]];
                float2 b = *(const float2*)&xW[((row + 8) * TLEN) * (4 * HDIM) + colg[ni]];
                nxt[mi][ni][0] = a.x; nxt[mi][ni][1] = a.y;
                nxt[mi][ni][2] = b.x; nxt[mi][ni][3] = b.y;
            }
        }
    }

    for (int t = 0; t < TLEN; t++) {
        float acc[2][NI][4];
#pragma unroll
        for (int mi = 0; mi < 2; mi++)
#pragma unroll
            for (int ni = 0; ni < NI; ni++) {
                if constexpr (KIN == 0) {
                    acc[mi][ni][0] = nxt[mi][ni][0]; acc[mi][ni][1] = nxt[mi][ni][1];
                    acc[mi][ni][2] = nxt[mi][ni][2]; acc[mi][ni][3] = nxt[mi][ni][3];
                } else {
                    acc[mi][ni][0] = bs[ni][0]; acc[mi][ni][1] = bs[ni][1];
                    acc[mi][ni][2] = bs[ni][0]; acc[mi][ni][3] = bs[ni][1];
                }
            }

        // U-phase GEMM over one K-half (compile-time half index)
        auto gemmU = [&](auto HC) {
            constexpr int half = decltype(HC)::value;
#pragma unroll
            for (int j = 0; j < KSUh; j++) {
                constexpr int base = half * KSUh;
                const int ks = base + j;
                uint32_t ahi[2][4], alo[2][4];
#pragma unroll
                for (int mi = 0; mi < 2; mi++) {
                    uint32_t aoff = (uint32_t)((wm * 32 + mi * 16 + aRowOff) * KS2U
                                               + ks * 16 + aColOff) * 2;
                    ldsm_x4(ahi[mi], uHhi + aoff);
                    ldsm_x4(alo[mi], uHlo + aoff);
                }
#pragma unroll
                for (int ni = 0; ni < NI; ni++) {
                    uint32_t bh[2], bl[2];
                    uint32_t boff = (uint32_t)((wn * WN + ni * 8 + r8) * KS2U
                                               + ks * 16 + bSel * 8) * 2;
                    if constexpr (HOIST) {
                        bh[0] = uHiReg[ks][ni][0]; bh[1] = uHiReg[ks][ni][1];
                    } else {
                        ldsm_x2(bh, uUhi + boff);
                    }
                    ldsm_x2(bl, uUlo + boff);
#pragma unroll
                    for (int mi = 0; mi < 2; mi++) {
                        mma_16816(acc[mi][ni], ahi[mi], bh);
                        mma_16816(acc[mi][ni], ahi[mi], bl);
                        mma_16816(acc[mi][ni], alo[mi], bh);
                    }
                }
            }
        };
        auto gemmW = [&](auto HC) {
            constexpr int half = decltype(HC)::value;
#pragma unroll
            for (int j = 0; j < KSWh; j++) {
                const int ks = half * KSWh + j;
                uint32_t ahi[2][4], alo[2][4];
#pragma unroll
                for (int mi = 0; mi < 2; mi++) {
                    uint32_t aoff = (uint32_t)((wm * 32 + mi * 16 + aRowOff) * KS2W
                                               + ks * 16 + aColOff) * 2;
                    ldsm_x4(ahi[mi], uHhi + aoff);
                    ldsm_x4(alo[mi], uHlo + aoff);
                }
#pragma unroll
                for (int ni = 0; ni < NI; ni++) {
                    uint32_t bh[2], bl[2];
                    uint32_t boff = (uint32_t)((wn * WN + ni * 8 + r8) * KS2W
                                               + ks * 16 + bSel * 8) * 2;
                    ldsm_x2(bh, uWhi + boff);
                    ldsm_x2(bl, uWlo + boff);
#pragma unroll
                    for (int mi = 0; mi < 2; mi++) {
                        mma_16816(acc[mi][ni], ahi[mi], bh);
                        mma_16816(acc[mi][ni], ahi[mi], bl);
                        mma_16816(acc[mi][ni], alo[mi], bh);
                    }
                }
            }
        };

        const size_t rsU = (size_t)TLEN * HDIM;
        const size_t gbU = ((size_t)b0 * TLEN + (t - 1)) * HDIM;

        if (t > 0) {
            wait_cnt_ge(selfslot, (unsigned)(GRPN * t));
            stage_half_async<U4Uh, KS2U>(tid, 0, Hhi, Hlo, gbU, rsU, uHhi, uHlo);
            CP_COMMIT();
            stage_half_async<U4Uh, KS2U>(tid, 1, Hhi, Hlo, gbU, rsU, uHhi, uHlo);
            CP_COMMIT();
            CP_WAIT1(); __syncthreads();         // half0 ready
            gemmU(IC<0>{});
            if constexpr (!OVERLAP || KIN == 0) {
                CP_WAIT0(); __syncthreads();     // half1 ready
                gemmU(IC<1>{});
            }
            __syncthreads();                      // reads of half0 done
        }

        if constexpr (KIN > 0) {
            const size_t rsW = (size_t)TLEN * KIN;
            const size_t gbW = ((size_t)b0 * TLEN + t) * KIN;
            wait_cnt_ge(prodslot, (unsigned)(PGRPN * (t + 1)));
            stage_half_async<U4Wh, KS2W>(tid, 0, Hin_hi, Hin_lo, gbW, rsW, uHhi, uHlo);
            CP_COMMIT();
            if constexpr (OVERLAP) {
                if (t > 0) {
                    CP_WAIT1(); __syncthreads(); // U half1 ready (W0 pending)
                    gemmU(IC<1>{});
                    __syncthreads();             // reads of half1 done
                }
            }
            stage_half_async<U4Wh, KS2W>(tid, 1, Hin_hi, Hin_lo, gbW, rsW, uHhi, uHlo);
            CP_COMMIT();
            CP_WAIT1(); __syncthreads();          // W half0 ready
            gemmW(IC<0>{});
            CP_WAIT0(); __syncthreads();          // W half1 ready
            gemmW(IC<1>{});
        }

        // Gates (even tp: i,f | odd tp: g,o of same unit); stage h out
#pragma unroll
        for (int mi = 0; mi < 2; mi++) {
#pragma unroll
            for (int ni = 0; ni < NI; ni++) {
                float v0, v1, v2, v3;
                if (evenp) {
                    v0 = sigf(acc[mi][ni][0]); v1 = sigf(acc[mi][ni][1]);
                    v2 = sigf(acc[mi][ni][2]); v3 = sigf(acc[mi][ni][3]);
                } else {
                    v0 = tanhf_(acc[mi][ni][0]); v1 = sigf(acc[mi][ni][1]);
                    v2 = tanhf_(acc[mi][ni][2]); v3 = sigf(acc[mi][ni][3]);
                }
                float p0 = __shfl_xor_sync(0xffffffffu, v0, 1);
                float p1 = __shfl_xor_sync(0xffffffffu, v1, 1);
                float p2 = __shfl_xor_sync(0xffffffffu, v2, 1);
                float p3 = __shfl_xor_sync(0xffffffffu, v3, 1);
                float i0 = evenp ? v0 : p0, f0 = evenp ? v1 : p1;
                float g0 = evenp ? p0 : v0, o0 = evenp ? p1 : v1;
                float i1 = evenp ? v2 : p2, f1 = evenp ? v3 : p3;
                float g1 = evenp ? p2 : v2, o1 = evenp ? p3 : v3;

                float c0 = fmaf(f0, cst[mi][ni][0], i0 * g0);
                float c1 = fmaf(f1, cst[mi][ni][1], i1 * g1);
                cst[mi][ni][0] = c0;
                cst[mi][ni][1] = c1;
                float h0 = o0 * tanhf_(c0);
                float h1 = o1 * tanhf_(c1);

                if (evenp) {
                    int r0 = wm * 32 + mi * 16 + tg, r1 = r0 + 8;
                    bf16 h0h = __float2bfloat16_rn(h0);
                    bf16 h1h = __float2bfloat16_rn(h1);
                    sSthi[r0 * UPCv + uLoc[ni]] = h0h;
                    sStlo[r0 * UPCv + uLoc[ni]] = __float2bfloat16_rn(h0 - __bfloat162float(h0h));
                    sSthi[r1 * UPCv + uLoc[ni]] = h1h;
                    sStlo[r1 * UPCv + uLoc[ni]] = __float2bfloat16_rn(h1 - __bfloat162float(h1h));
                }
            }
        }

        // L0: prefetch next xW (hidden under store)
        if constexpr (KIN == 0) {
            if (t + 1 < TLEN) {
#pragma unroll
                for (int mi = 0; mi < 2; mi++) {
                    size_t row = (size_t)(b0 + wm * 32 + mi * 16 + tg);
#pragma unroll
                    for (int ni = 0; ni < NI; ni++) {
                        float2 a = *(const float2*)&xW[(row * TLEN + t + 1) * (4 * HDIM) + colg[ni]];
                        float2 b = *(const float2*)&xW[((row + 8) * TLEN + t + 1) * (4 * HDIM) + colg[ni]];
                        nxt[mi][ni][0] = a.x; nxt[mi][ni][1] = a.y;
                        nxt[mi][ni][2] = b.x; nxt[mi][ni][3] = b.y;
                    }
                }
            }
        }

        __syncthreads();
        // Coalesced h store (hi & lo)
        for (int idx = tid; idx < 64 * STW; idx += 256) {
            int r = idx / STW, q = idx - r * STW;
            size_t g = ((size_t)(b0 + r) * TLEN + t) * HDIM + cb * UPCv + q * 2;
            *(uint32_t*)&Hhi[g] = ((const uint32_t*)sSthi)[r * STW + q];
            *(uint32_t*)&Hlo[g] = ((const uint32_t*)sStlo)[r * STW + q];
        }

        arrive_cnt(selfslot);   // publish this round (non-blocking)
    }
}

__global__ __launch_bounds__(256, 1) void fused_lstm()
{
    int bx = blockIdx.x;
    if (bx < 32) {
        int bb = bx >> 3, cb = bx & 7;
        run_layer<256, 0, 32, 8, 1>(bb, cb, bb, -1,
            g_Uthi + UOFF0, g_Utlo + UOFF0, nullptr, nullptr,
            nullptr, g_xW, nullptr, nullptr, g_H0hi, g_H0lo);
    } else if (bx < 96) {
        int l = bx - 32;
        int bb = l >> 4, cb = l & 15;
        run_layer<256, 256, 16, 16, 8>(bb, cb, 4 + bb, bb,
            g_Uthi + UOFF1, g_Utlo + UOFF1, g_Wthi + WOFF1, g_Wtlo + WOFF1,
            g_biasP, nullptr, g_H0hi, g_H0lo, g_H1hi, g_H1lo);
    } else {
        int l = bx - 96;
        int bb = l >> 3, cb = l & 7;
        run_layer<128, 256, 16, 8, 16>(bb, cb, 8 + bb, 4 + bb,
            g_Uthi + UOFF2, g_Utlo + UOFF2, g_Wthi + WOFF2, g_Wtlo + WOFF2,
            g_biasP + 1024, nullptr, g_H1hi, g_H1lo, g_H2hi, g_H2lo);
    }
}

// ---------------------------------------------------------------------------
// Final dense: out[b,d] = (hi+lo)[b,T-1,:128] @ Wd + bd
// ---------------------------------------------------------------------------
__global__ void dense_kernel(const float* __restrict__ Wd, const float* __restrict__ bd,
                             float* __restrict__ out)
{
    int b = blockIdx.x;
    int d = threadIdx.x;
    size_t base = ((size_t)b * TLEN + (TLEN - 1)) * 128;
    float acc = 0.f;
#pragma unroll 4
    for (int k = 0; k < 128; k++) {
        float h = __bfloat162float(g_H2hi[base + k]) + __bfloat162float(g_H2lo[base + k]);
        acc = fmaf(h, Wd[k * 64 + d], acc);
    }
    out[b * 64 + d] = acc + bd[d];
}

// ---------------------------------------------------------------------------
// Launch sequence: [0] conv_all  [1] conv_split  [2] mma_gemm
//                  [3] fused_lstm (ncu target)  [4] dense
// ---------------------------------------------------------------------------
#define FUSED_SMEM ((128 * 264 * 2 + 64 * 264 * 2 + 64 * 32 * 2) * 2)

extern "C" void kernel_launch(void* const* d_in, const int* in_sizes, int n_in,
                              void* d_out, int out_size)
{
    (void)in_sizes; (void)n_in; (void)out_size;
    const float* x  = (const float*)d_in[0];
    const float* W0 = (const float*)d_in[1];
    const float* U0 = (const float*)d_in[2];
    const float* b0 = (const float*)d_in[3];
    const float* W1 = (const float*)d_in[4];
    const float* U1 = (const float*)d_in[5];
    const float* b1 = (const float*)d_in[6];
    const float* W2 = (const float*)d_in[7];
    const float* U2 = (const float*)d_in[8];
    const float* b2 = (const float*)d_in[9];
    const float* Wd = (const float*)d_in[10];
    const float* bd = (const float*)d_in[11];
    float* out = (float*)d_out;

    void* p;
    cudaGetSymbolAddress(&p, g_xW);    float* xw = (float*)p;
    cudaGetSymbolAddress(&p, g_Ahi);   bf16* ahi = (bf16*)p;
    cudaGetSymbolAddress(&p, g_Alo);   bf16* alo = (bf16*)p;
    cudaGetSymbolAddress(&p, g_Wthi);  bf16* whi = (bf16*)p;
    cudaGetSymbolAddress(&p, g_Wtlo);  bf16* wlo = (bf16*)p;
    cudaGetSymbolAddress(&p, g_Uthi);  bf16* uhi = (bf16*)p;
    cudaGetSymbolAddress(&p, g_Utlo);  bf16* ulo = (bf16*)p;
    cudaGetSymbolAddress(&p, g_bias);  float* bp0 = (float*)p;
    cudaGetSymbolAddress(&p, g_biasP); float* bpP = (float*)p;

    cudaFuncSetAttribute(mma_gemm, cudaFuncAttributeMaxDynamicSharedMemorySize, GEMM_SMEM);
    cudaFuncSetAttribute(fused_lstm, cudaFuncAttributeMaxDynamicSharedMemorySize, FUSED_SMEM);

    // [0] all weight/bias conversion + counter reset (one launch)
    conv_all<<<4108, 256>>>(W0, W1, W2, U0, U1, U2, b0, b1, b2,
                            whi, wlo, uhi, ulo, bp0, bpP);
    // [1] x split
    conv_split<<<(MTOT * 64 / 4 + 255) / 256, 256>>>(x, ahi, alo, MTOT * 64 / 4);
    // [2] layer-0 xW precompute
    mma_gemm<<<dim3(8, MTOT / 128), 256, GEMM_SMEM>>>(ahi, alo, whi + WOFF0, wlo + WOFF0,
                                                      bp0, xw, 64, 1024);
    // [3] fused wavefront (profiling target)
    fused_lstm<<<128, 256, FUSED_SMEM>>>();
    // [4] dense head
    dense_kernel<<<BSZ, 64>>>(Wd, bd, out);
}